// round 6
// baseline (speedup 1.0000x reference)
#include <cuda_runtime.h>
#include <cuda_bf16.h>
#include <math.h>
#include <stdint.h>

#define DIM 1024
#define HIDDEN 2048
#define NE 8
#define TOKENS 2048
#define NSLOT (2*TOKENS)

// ---------------- scratch (static device globals; no runtime alloc) ----------
__device__ int   g_cnt[NE];
__device__ int   g_slots[NE * TOKENS];
__device__ float g_w[NSLOT];
__device__ float g_h2[(size_t)NSLOT * HIDDEN];   // relu^2 activations, fp32 (32 MB)

// ---------------- helpers -----------------------------------------------------
__device__ __forceinline__ uint32_t smem_u32(const void* p) {
    uint32_t a;
    asm("{ .reg .u64 t; cvta.to.shared.u64 t, %1; cvt.u32.u64 %0, t; }"
        : "=r"(a) : "l"(p));
    return a;
}
__device__ __forceinline__ uint32_t sw128(uint32_t b) { return b ^ ((b >> 3) & 0x70); }

__device__ __forceinline__ void ldm_x4(uint32_t* r, uint32_t addr) {
    asm volatile("ldmatrix.sync.aligned.m8n8.x4.shared.b16 {%0,%1,%2,%3}, [%4];"
                 : "=r"(r[0]), "=r"(r[1]), "=r"(r[2]), "=r"(r[3]) : "r"(addr));
}
__device__ __forceinline__ void mma_bf16(float* d, const uint32_t* a, const uint32_t* b) {
    asm volatile(
        "mma.sync.aligned.m16n8k16.row.col.f32.bf16.bf16.f32 "
        "{%0,%1,%2,%3}, {%4,%5,%6,%7}, {%8,%9}, {%0,%1,%2,%3};"
        : "+f"(d[0]), "+f"(d[1]), "+f"(d[2]), "+f"(d[3])
        : "r"(a[0]), "r"(a[1]), "r"(a[2]), "r"(a[3]), "r"(b[0]), "r"(b[1]));
}
__device__ __forceinline__ uint32_t pack_hi(float a, float b) {
    __nv_bfloat16 ha = __float2bfloat16(a), hb = __float2bfloat16(b);
    return (uint32_t)__bfloat16_as_ushort(ha) |
           ((uint32_t)__bfloat16_as_ushort(hb) << 16);
}
__device__ __forceinline__ uint32_t pack_lo(float a, float b) {
    __nv_bfloat16 ha = __float2bfloat16(a), hb = __float2bfloat16(b);
    float la = a - __bfloat162float(ha);
    float lb = b - __bfloat162float(hb);
    __nv_bfloat16 hla = __float2bfloat16(la), hlb = __float2bfloat16(lb);
    return (uint32_t)__bfloat16_as_ushort(hla) |
           ((uint32_t)__bfloat16_as_ushort(hlb) << 16);
}
// 8 fp32 (two float4) -> hi uint4 + lo uint4
__device__ __forceinline__ void split8(const float4& v0, const float4& v1,
                                       uint4& hi, uint4& lo) {
    hi.x = pack_hi(v0.x, v0.y); hi.y = pack_hi(v0.z, v0.w);
    hi.z = pack_hi(v1.x, v1.y); hi.w = pack_hi(v1.z, v1.w);
    lo.x = pack_lo(v0.x, v0.y); lo.y = pack_lo(v0.z, v0.w);
    lo.z = pack_lo(v1.x, v1.y); lo.w = pack_lo(v1.z, v1.w);
}

// ---------------- zero counters / zero output --------------------------------
__global__ void zero_cnt_kernel() {
    if (threadIdx.x < NE) g_cnt[threadIdx.x] = 0;
}
__global__ void zero_out_kernel(float* __restrict__ out, int out_size) {
    int i = blockIdx.x * blockDim.x + threadIdx.x;
    int n4 = out_size >> 2;
    if (i < n4) ((float4*)out)[i] = make_float4(0.f, 0.f, 0.f, 0.f);
    if (i == 0) {
        for (int j = n4 << 2; j < out_size; j++) out[j] = 0.f;
    }
}

// ---------------- router ------------------------------------------------------
__global__ void router_kernel(const float* __restrict__ x,
                              const float* __restrict__ Wr) {
    int warp = threadIdx.x >> 5;
    int lane = threadIdx.x & 31;
    int t = blockIdx.x * 8 + warp;
    if (t >= TOKENS) return;

    float acc[NE];
#pragma unroll
    for (int e = 0; e < NE; e++) acc[e] = 0.f;
    const float* xr = x + (size_t)t * DIM;
    for (int d = lane; d < DIM; d += 32) {
        float xv = xr[d];
#pragma unroll
        for (int e = 0; e < NE; e++) acc[e] += xv * Wr[e * DIM + d];
    }
#pragma unroll
    for (int e = 0; e < NE; e++) {
#pragma unroll
        for (int o = 16; o > 0; o >>= 1)
            acc[e] += __shfl_xor_sync(0xffffffffu, acc[e], o);
    }
    if (lane == 0) {
        float mx = acc[0];
#pragma unroll
        for (int e = 1; e < NE; e++) mx = fmaxf(mx, acc[e]);
        float p[NE]; float Z = 0.f;
#pragma unroll
        for (int e = 0; e < NE; e++) { p[e] = expf(acc[e] - mx); Z += p[e]; }
        int i1 = 0; float b1 = -1.f;
#pragma unroll
        for (int e = 0; e < NE; e++) if (p[e] > b1) { b1 = p[e]; i1 = e; }
        int i2 = -1; float b2 = -1.f;
#pragma unroll
        for (int e = 0; e < NE; e++) if (e != i1 && p[e] > b2) { b2 = p[e]; i2 = e; }
        float p1 = b1 / Z, p2 = b2 / Z;
        float s = p1 + p2 + 1e-8f;
        int pos1 = atomicAdd(&g_cnt[i1], 1);
        g_slots[i1 * TOKENS + pos1] = 2 * t;
        g_w[2 * t] = p1 / s;
        int pos2 = atomicAdd(&g_cnt[i2], 1);
        g_slots[i2 * TOKENS + pos2] = 2 * t + 1;
        g_w[2 * t + 1] = p2 / s;
    }
}

// ---------------- fused-split HMMA grouped GEMM -------------------------------
// C[128,128] fp32 = sum_K A*B, operands fp32 in GMEM, split to bf16 hi/lo in
// registers at load time (traffic-neutral: 4B fp32 == 2B hi + 2B lo).
// 3-term HMMA: hi*hi + hi*lo + lo*hi. Double-buffered SMEM (2 x 64KB), one
// __syncthreads per k-slab; STS(k+1) targets opposite stage of compute(k).
// MODE 0 (fc):   A = x[slot>>1],  K=DIM,   B = W_fc,  epi relu^2 -> g_h2 fp32
// MODE 1 (proj): A = g_h2[slot],  K=HIDDEN,B = W_proj, epi wgt*acc atomicAdd->out
#define OFF_AHI 0
#define OFF_ALO 16384
#define OFF_BHI 32768
#define OFF_BLO 49152
#define STAGE_BYTES 65536
#define SMEM_TOTAL (2 * STAGE_BYTES)

template <int K, int NTOT, int MODE>
__global__ void __launch_bounds__(512, 1) moe_mma_gemm(
    const float* __restrict__ A,   // x (MODE 0) or g_h2 (MODE 1)
    const float* __restrict__ B,   // W_fc / W_proj (full, expert-major)
    float* __restrict__ out) {
    const int e = blockIdx.z;
    const int cnt = g_cnt[e];
    const int m0 = blockIdx.y * 128;
    if (m0 >= cnt) return;
    const int n0 = blockIdx.x * 128;
    const int* slots = g_slots + e * TOKENS;

    extern __shared__ char smem[];
    const uint32_t sb = smem_u32(smem);
    const int tid = threadIdx.x;
    const int lane = tid & 31;
    const int wid = tid >> 5;
    const int wm = wid & 3;       // m-block of 32
    const int wn = wid >> 2;      // n-block of 32

    // loader: thread covers rows r0l and r0l+64, 16B bf16 chunk c16 (8 k-vals)
    const int c16 = tid & 7;
    const int r0l = tid >> 3;  // 0..63

    const float* asrc[2];
    const float* bsrc[2];
    bool aok[2];
    uint32_t swoff[2];
#pragma unroll
    for (int p = 0; p < 2; p++) {
        int row = r0l + 64 * p;
        swoff[p] = sw128((uint32_t)(row * 128 + c16 * 16));
        int m = m0 + row;
        if (m < cnt) {
            int slot = slots[m];
            int arow = (MODE == 0) ? (slot >> 1) : slot;
            asrc[p] = A + (size_t)arow * K + c16 * 8;
            aok[p] = true;
        } else {
            asrc[p] = A;
            aok[p] = false;
        }
        bsrc[p] = B + ((size_t)e * NTOT + n0 + row) * K + c16 * 8;
    }

    // ldmatrix address components (within-tile byte offsets before swizzle)
    const uint32_t a_row = wm * 32 + (lane & 15);
    const uint32_t a_kb = (uint32_t)((lane >> 4) << 4);
    const uint32_t b_row = wn * 32 + (lane & 7) + ((lane >> 4) << 3);
    const uint32_t b_kb = (uint32_t)(((lane >> 3) & 1) << 4);

    float acc[2][4][4];
#pragma unroll
    for (int i = 0; i < 2; i++)
#pragma unroll
        for (int j = 0; j < 4; j++)
#pragma unroll
            for (int q = 0; q < 4; q++) acc[i][j][q] = 0.f;

    constexpr int NK = K / 64;
    const float4 z4 = make_float4(0.f, 0.f, 0.f, 0.f);

    float4 ar[2][2], br[2][2];

    // --- prologue: load slab 0, STS stage 0, load slab 1 ---
#pragma unroll
    for (int p = 0; p < 2; p++) {
        ar[p][0] = aok[p] ? ((const float4*)asrc[p])[0] : z4;
        ar[p][1] = aok[p] ? ((const float4*)asrc[p])[1] : z4;
        br[p][0] = ((const float4*)bsrc[p])[0];
        br[p][1] = ((const float4*)bsrc[p])[1];
    }
#pragma unroll
    for (int p = 0; p < 2; p++) {
        uint4 hi, lo;
        split8(ar[p][0], ar[p][1], hi, lo);
        *(uint4*)(smem + OFF_AHI + swoff[p]) = hi;
        *(uint4*)(smem + OFF_ALO + swoff[p]) = lo;
        split8(br[p][0], br[p][1], hi, lo);
        *(uint4*)(smem + OFF_BHI + swoff[p]) = hi;
        *(uint4*)(smem + OFF_BLO + swoff[p]) = lo;
    }
    if (NK > 1) {
#pragma unroll
        for (int p = 0; p < 2; p++) {
            ar[p][0] = aok[p] ? ((const float4*)(asrc[p] + 64))[0] : z4;
            ar[p][1] = aok[p] ? ((const float4*)(asrc[p] + 64))[1] : z4;
            br[p][0] = ((const float4*)(bsrc[p] + 64))[0];
            br[p][1] = ((const float4*)(bsrc[p] + 64))[1];
        }
    }
    __syncthreads();

    for (int kt = 0; kt < NK; kt++) {
        // STS slab kt+1 (regs hold it) into opposite stage
        if (kt + 1 < NK) {
            char* dst = smem + ((kt + 1) & 1) * STAGE_BYTES;
#pragma unroll
            for (int p = 0; p < 2; p++) {
                uint4 hi, lo;
                split8(ar[p][0], ar[p][1], hi, lo);
                *(uint4*)(dst + OFF_AHI + swoff[p]) = hi;
                *(uint4*)(dst + OFF_ALO + swoff[p]) = lo;
                split8(br[p][0], br[p][1], hi, lo);
                *(uint4*)(dst + OFF_BHI + swoff[p]) = hi;
                *(uint4*)(dst + OFF_BLO + swoff[p]) = lo;
            }
        }
        // LDG slab kt+2
        if (kt + 2 < NK) {
            int kn = (kt + 2) * 64;
#pragma unroll
            for (int p = 0; p < 2; p++) {
                ar[p][0] = aok[p] ? ((const float4*)(asrc[p] + kn))[0] : z4;
                ar[p][1] = aok[p] ? ((const float4*)(asrc[p] + kn))[1] : z4;
                br[p][0] = ((const float4*)(bsrc[p] + kn))[0];
                br[p][1] = ((const float4*)(bsrc[p] + kn))[1];
            }
        }

        // compute slab kt from stage kt&1
        const uint32_t base = sb + (kt & 1) * STAGE_BYTES;
#pragma unroll
        for (int c = 0; c < 4; c++) {
            const uint32_t kb = (uint32_t)(c * 32);
            uint32_t ah[2][4], al[2][4], bh[2][4], bl[2][4];
#pragma unroll
            for (int i = 0; i < 2; i++) {
                uint32_t off = sw128((a_row + 16 * i) * 128 + kb + a_kb);
                ldm_x4(ah[i], base + OFF_AHI + off);
                ldm_x4(al[i], base + OFF_ALO + off);
            }
#pragma unroll
            for (int jj = 0; jj < 2; jj++) {
                uint32_t off = sw128((b_row + 16 * jj) * 128 + kb + b_kb);
                ldm_x4(bh[jj], base + OFF_BHI + off);
                ldm_x4(bl[jj], base + OFF_BLO + off);
            }
#pragma unroll
            for (int i = 0; i < 2; i++)
#pragma unroll
                for (int j = 0; j < 4; j++) {
                    const uint32_t* bhp = &bh[j >> 1][(j & 1) * 2];
                    const uint32_t* blp = &bl[j >> 1][(j & 1) * 2];
                    mma_bf16(acc[i][j], ah[i], bhp);
                    mma_bf16(acc[i][j], ah[i], blp);
                    mma_bf16(acc[i][j], al[i], bhp);
                }
        }
        __syncthreads();
    }

    // epilogue
    const int gid = lane >> 2;
    const int tig = lane & 3;
#pragma unroll
    for (int i = 0; i < 2; i++) {
#pragma unroll
        for (int h = 0; h < 2; h++) {
            int mrow = m0 + wm * 32 + i * 16 + gid + 8 * h;
            if (mrow >= cnt) continue;
            int slot = slots[mrow];
            if (MODE == 0) {
                float* hr = g_h2 + (size_t)slot * HIDDEN + n0;
#pragma unroll
                for (int j = 0; j < 4; j++) {
                    int col = wn * 32 + j * 8 + 2 * tig;
#pragma unroll
                    for (int q = 0; q < 2; q++) {
                        float v = acc[i][j][h * 2 + q];
                        v = fmaxf(v, 0.f);
                        hr[col + q] = v * v;
                    }
                }
            } else {
                float wgt = g_w[slot];
                int token = slot >> 1;
                float* orow = out + (size_t)token * DIM + n0;
#pragma unroll
                for (int j = 0; j < 4; j++) {
                    int col = wn * 32 + j * 8 + 2 * tig;
                    atomicAdd(&orow[col + 0], wgt * acc[i][j][h * 2 + 0]);
                    atomicAdd(&orow[col + 1], wgt * acc[i][j][h * 2 + 1]);
                }
            }
        }
    }
}

// ---------------- launch ------------------------------------------------------
extern "C" void kernel_launch(void* const* d_in, const int* in_sizes, int n_in,
                              void* d_out, int out_size) {
    const float* x = (const float*)d_in[0];
    const float* Wr = (const float*)d_in[1];
    const float* Wfc = (const float*)d_in[2];
    const float* Wpj = (const float*)d_in[3];
    float* out = (float*)d_out;

    cudaFuncSetAttribute(moe_mma_gemm<DIM, HIDDEN, 0>,
                         cudaFuncAttributeMaxDynamicSharedMemorySize, SMEM_TOTAL);
    cudaFuncSetAttribute(moe_mma_gemm<HIDDEN, DIM, 1>,
                         cudaFuncAttributeMaxDynamicSharedMemorySize, SMEM_TOTAL);

    float* h2ptr;
    cudaGetSymbolAddress((void**)&h2ptr, g_h2);

    zero_cnt_kernel<<<1, 32>>>();
    zero_out_kernel<<<(out_size / 4 + 255) / 256, 256>>>(out, out_size);
    router_kernel<<<TOKENS / 8, 256>>>(x, Wr);

    // fc: N=HIDDEN, K=DIM   (splits x and W_fc inline)
    moe_mma_gemm<DIM, HIDDEN, 0>
        <<<dim3(HIDDEN / 128, TOKENS / 128, NE), 512, SMEM_TOTAL>>>(x, Wfc, out);
    // proj: N=DIM, K=HIDDEN (splits g_h2 and W_proj inline; accumulates into out)
    moe_mma_gemm<HIDDEN, DIM, 1>
        <<<dim3(DIM / 128, TOKENS / 128, NE), 512, SMEM_TOTAL>>>(h2ptr, Wpj, out);
}

// round 8
// speedup vs baseline: 1.0905x; 1.0905x over previous
#include <cuda_runtime.h>
#include <cuda_bf16.h>
#include <math.h>
#include <stdint.h>

#define DIM 1024
#define HIDDEN 2048
#define NE 8
#define TOKENS 2048
#define NSLOT (2*TOKENS)

// ---------------- scratch (static device globals; no runtime alloc) ----------
__device__ int   g_cnt[NE];
__device__ int   g_slots[NE * TOKENS];
__device__ float g_w[NSLOT];

__device__ __nv_bfloat16 g_xhi[(size_t)TOKENS * DIM];
__device__ __nv_bfloat16 g_xlo[(size_t)TOKENS * DIM];
__device__ __nv_bfloat16 g_wfchi[(size_t)NE * HIDDEN * DIM];
__device__ __nv_bfloat16 g_wfclo[(size_t)NE * HIDDEN * DIM];
__device__ __nv_bfloat16 g_wpjhi[(size_t)NE * DIM * HIDDEN];
__device__ __nv_bfloat16 g_wpjlo[(size_t)NE * DIM * HIDDEN];
__device__ __nv_bfloat16 g_h2hi[(size_t)NSLOT * HIDDEN];
__device__ __nv_bfloat16 g_h2lo[(size_t)NSLOT * HIDDEN];

// ---------------- helpers -----------------------------------------------------
__device__ __forceinline__ uint32_t smem_u32(const void* p) {
    uint32_t a;
    asm("{ .reg .u64 t; cvta.to.shared.u64 t, %1; cvt.u32.u64 %0, t; }"
        : "=r"(a) : "l"(p));
    return a;
}
__device__ __forceinline__ uint32_t sw128(uint32_t b) { return b ^ ((b >> 3) & 0x70); }

__device__ __forceinline__ void ldm_x4(uint32_t* r, uint32_t addr) {
    asm volatile("ldmatrix.sync.aligned.m8n8.x4.shared.b16 {%0,%1,%2,%3}, [%4];"
                 : "=r"(r[0]), "=r"(r[1]), "=r"(r[2]), "=r"(r[3]) : "r"(addr));
}
__device__ __forceinline__ void mma_bf16(float* d, const uint32_t* a, const uint32_t* b) {
    asm volatile(
        "mma.sync.aligned.m16n8k16.row.col.f32.bf16.bf16.f32 "
        "{%0,%1,%2,%3}, {%4,%5,%6,%7}, {%8,%9}, {%0,%1,%2,%3};"
        : "+f"(d[0]), "+f"(d[1]), "+f"(d[2]), "+f"(d[3])
        : "r"(a[0]), "r"(a[1]), "r"(a[2]), "r"(a[3]), "r"(b[0]), "r"(b[1]));
}
__device__ __forceinline__ void cp16(uint32_t dst, const void* src, uint32_t srcsize) {
    asm volatile("cp.async.cg.shared.global [%0], [%1], 16, %2;"
                 :: "r"(dst), "l"(src), "r"(srcsize) : "memory");
}
__device__ __forceinline__ void cp_commit() {
    asm volatile("cp.async.commit_group;" ::: "memory");
}
template <int N>
__device__ __forceinline__ void cp_wait() {
    asm volatile("cp.async.wait_group %0;" :: "n"(N) : "memory");
}

// ---------------- zero counters / zero output --------------------------------
__global__ void zero_cnt_kernel() {
    if (threadIdx.x < NE) g_cnt[threadIdx.x] = 0;
}
__global__ void zero_out_kernel(float* __restrict__ out, int out_size) {
    int i = blockIdx.x * blockDim.x + threadIdx.x;
    int n4 = out_size >> 2;
    if (i < n4) ((float4*)out)[i] = make_float4(0.f, 0.f, 0.f, 0.f);
    if (i == 0) {
        for (int j = n4 << 2; j < out_size; j++) out[j] = 0.f;
    }
}

// ---------------- fp32 -> bf16 hi/lo split (4 float4 per thread) --------------
template <int WHICH>  // 0 = x, 1 = W_fc, 2 = W_proj
__global__ void split_kernel(const float* __restrict__ src, int n4) {
    __nv_bfloat16* hi = (WHICH == 0) ? g_xhi : (WHICH == 1) ? g_wfchi : g_wpjhi;
    __nv_bfloat16* lo = (WHICH == 0) ? g_xlo : (WHICH == 1) ? g_wfclo : g_wpjlo;
    int base = blockIdx.x * (blockDim.x * 4) + threadIdx.x;
#pragma unroll
    for (int k = 0; k < 4; k++) {
        int i = base + k * blockDim.x;
        if (i >= n4) return;
        float4 v = ((const float4*)src)[i];
        __nv_bfloat16 h0 = __float2bfloat16(v.x);
        __nv_bfloat16 h1 = __float2bfloat16(v.y);
        __nv_bfloat16 h2 = __float2bfloat16(v.z);
        __nv_bfloat16 h3 = __float2bfloat16(v.w);
        __nv_bfloat16 l0 = __float2bfloat16(v.x - __bfloat162float(h0));
        __nv_bfloat16 l1 = __float2bfloat16(v.y - __bfloat162float(h1));
        __nv_bfloat16 l2 = __float2bfloat16(v.z - __bfloat162float(h2));
        __nv_bfloat16 l3 = __float2bfloat16(v.w - __bfloat162float(h3));
        __nv_bfloat162* hp = (__nv_bfloat162*)(hi + (size_t)i * 4);
        __nv_bfloat162* lp = (__nv_bfloat162*)(lo + (size_t)i * 4);
        hp[0] = __nv_bfloat162(h0, h1); hp[1] = __nv_bfloat162(h2, h3);
        lp[0] = __nv_bfloat162(l0, l1); lp[1] = __nv_bfloat162(l2, l3);
    }
}

// ---------------- router ------------------------------------------------------
__global__ void router_kernel(const float* __restrict__ x,
                              const float* __restrict__ Wr) {
    int warp = threadIdx.x >> 5;
    int lane = threadIdx.x & 31;
    int t = blockIdx.x * 8 + warp;
    if (t >= TOKENS) return;

    float acc[NE];
#pragma unroll
    for (int e = 0; e < NE; e++) acc[e] = 0.f;
    const float* xr = x + (size_t)t * DIM;
    for (int d = lane; d < DIM; d += 32) {
        float xv = xr[d];
#pragma unroll
        for (int e = 0; e < NE; e++) acc[e] += xv * Wr[e * DIM + d];
    }
#pragma unroll
    for (int e = 0; e < NE; e++) {
#pragma unroll
        for (int o = 16; o > 0; o >>= 1)
            acc[e] += __shfl_xor_sync(0xffffffffu, acc[e], o);
    }
    if (lane == 0) {
        float mx = acc[0];
#pragma unroll
        for (int e = 1; e < NE; e++) mx = fmaxf(mx, acc[e]);
        float p[NE]; float Z = 0.f;
#pragma unroll
        for (int e = 0; e < NE; e++) { p[e] = expf(acc[e] - mx); Z += p[e]; }
        int i1 = 0; float b1 = -1.f;
#pragma unroll
        for (int e = 0; e < NE; e++) if (p[e] > b1) { b1 = p[e]; i1 = e; }
        int i2 = -1; float b2 = -1.f;
#pragma unroll
        for (int e = 0; e < NE; e++) if (e != i1 && p[e] > b2) { b2 = p[e]; i2 = e; }
        float p1 = b1 / Z, p2 = b2 / Z;
        float s = p1 + p2 + 1e-8f;
        int pos1 = atomicAdd(&g_cnt[i1], 1);
        g_slots[i1 * TOKENS + pos1] = 2 * t;
        g_w[2 * t] = p1 / s;
        int pos2 = atomicAdd(&g_cnt[i2], 1);
        g_slots[i2 * TOKENS + pos2] = 2 * t + 1;
        g_w[2 * t + 1] = p2 / s;
    }
}

// ---------------- HMMA grouped GEMM (3-stage cp.async) ------------------------
// C[128,128] fp32 = sum_K A*B with bf16 2-term split: hi*hi + hi*lo + lo*hi.
// 3-stage cp.async pipeline (stage = 64KB), two slabs in flight.
// Invariant: slab s lives in stage s % NSTAGE.
//   compute(kt) reads stage kt % 3; refill after compute(kt) issues slab kt+2
//   into stage (kt+2) % 3  (free since consumed at kt-1).
// MODE 0 (fc):   A = x[slot>>1],  K=DIM,   B = W_fc,  epi relu^2 -> h2 hi/lo
// MODE 1 (proj): A = h2[slot],    K=HIDDEN,B = W_proj, epi wgt*acc atomicAdd->out
#define OFF_AHI 0
#define OFF_ALO 16384
#define OFF_BHI 32768
#define OFF_BLO 49152
#define STAGE_BYTES 65536
#define NSTAGE 3
#define SMEM_TOTAL (NSTAGE * STAGE_BYTES)

template <int K, int NTOT, int MODE>
__global__ void __launch_bounds__(512, 1) moe_mma_gemm(float* __restrict__ out) {
    const int e = blockIdx.z;
    const int cnt = g_cnt[e];
    const int m0 = blockIdx.y * 128;
    if (m0 >= cnt) return;
    const int n0 = blockIdx.x * 128;
    const int* slots = g_slots + e * TOKENS;

    extern __shared__ char smem[];
    const uint32_t sb = smem_u32(smem);
    const int tid = threadIdx.x;
    const int lane = tid & 31;
    const int wid = tid >> 5;
    const int wm = wid & 3;       // m-block of 32
    const int wn = wid >> 2;      // n-block of 32

    const __nv_bfloat16* Ahi_base = (MODE == 0) ? g_xhi : g_h2hi;
    const __nv_bfloat16* Alo_base = (MODE == 0) ? g_xlo : g_h2lo;
    const __nv_bfloat16* Bhi_base = (MODE == 0) ? g_wfchi : g_wpjhi;
    const __nv_bfloat16* Blo_base = (MODE == 0) ? g_wfclo : g_wpjlo;

    // loader: thread covers rows r0l and r0l+64, 16B chunk c16 of 128B row
    const int c16 = tid & 7;
    const int r0l = tid >> 3;  // 0..63

    const __nv_bfloat16* aphi[2];
    const __nv_bfloat16* aplo[2];
    const __nv_bfloat16* bphi[2];
    const __nv_bfloat16* bplo[2];
    uint32_t asz[2];
    uint32_t swoff[2];
#pragma unroll
    for (int p = 0; p < 2; p++) {
        int row = r0l + 64 * p;
        swoff[p] = sw128((uint32_t)(row * 128 + c16 * 16));
        int m = m0 + row;
        if (m < cnt) {
            int slot = slots[m];
            int arow = (MODE == 0) ? (slot >> 1) : slot;
            aphi[p] = Ahi_base + (size_t)arow * K + c16 * 8;
            aplo[p] = Alo_base + (size_t)arow * K + c16 * 8;
            asz[p] = 16u;
        } else {
            aphi[p] = Ahi_base; aplo[p] = Alo_base; asz[p] = 0u;
        }
        size_t boff = ((size_t)e * NTOT + n0 + row) * K + c16 * 8;
        bphi[p] = Bhi_base + boff;
        bplo[p] = Blo_base + boff;
    }

    // ldmatrix address components (within-tile byte offsets before swizzle)
    const uint32_t a_row = wm * 32 + (lane & 15);
    const uint32_t a_kb = (uint32_t)((lane >> 4) << 4);
    const uint32_t b_row = wn * 32 + (lane & 7) + ((lane >> 4) << 3);
    const uint32_t b_kb = (uint32_t)(((lane >> 3) & 1) << 4);

    float acc[2][4][4];
#pragma unroll
    for (int i = 0; i < 2; i++)
#pragma unroll
        for (int j = 0; j < 4; j++)
#pragma unroll
            for (int q = 0; q < 4; q++) acc[i][j][q] = 0.f;

    constexpr int NK = K / 64;

    // issue slab into its stage (stage = slab % NSTAGE)
    auto issue = [&](int slab) {
        uint32_t base = sb + (slab % NSTAGE) * STAGE_BYTES;
        int kn = slab * 64;
#pragma unroll
        for (int p = 0; p < 2; p++) {
            cp16(base + OFF_AHI + swoff[p], aphi[p] + kn, asz[p]);
            cp16(base + OFF_ALO + swoff[p], aplo[p] + kn, asz[p]);
            cp16(base + OFF_BHI + swoff[p], bphi[p] + kn, 16u);
            cp16(base + OFF_BLO + swoff[p], bplo[p] + kn, 16u);
        }
        cp_commit();
    };

    // prologue: two slabs in flight
    issue(0);
    if (NK > 1) issue(1);

    for (int kt = 0; kt < NK; kt++) {
        if (kt + 1 < NK) cp_wait<1>(); else cp_wait<0>();
        __syncthreads();

        const uint32_t base = sb + (kt % NSTAGE) * STAGE_BYTES;
#pragma unroll
        for (int c = 0; c < 4; c++) {
            const uint32_t kb = (uint32_t)(c * 32);
            uint32_t ah[2][4], al[2][4], bh[2][4], bl[2][4];
#pragma unroll
            for (int i = 0; i < 2; i++) {
                uint32_t off = sw128((a_row + 16 * i) * 128 + kb + a_kb);
                ldm_x4(ah[i], base + OFF_AHI + off);
                ldm_x4(al[i], base + OFF_ALO + off);
            }
#pragma unroll
            for (int jj = 0; jj < 2; jj++) {
                uint32_t off = sw128((b_row + 16 * jj) * 128 + kb + b_kb);
                ldm_x4(bh[jj], base + OFF_BHI + off);
                ldm_x4(bl[jj], base + OFF_BLO + off);
            }
#pragma unroll
            for (int i = 0; i < 2; i++)
#pragma unroll
                for (int j = 0; j < 4; j++) {
                    const uint32_t* bhp = &bh[j >> 1][(j & 1) * 2];
                    const uint32_t* blp = &bl[j >> 1][(j & 1) * 2];
                    mma_bf16(acc[i][j], ah[i], bhp);
                    mma_bf16(acc[i][j], ah[i], blp);
                    mma_bf16(acc[i][j], al[i], bhp);
                }
        }
        __syncthreads();

        // refill: slab kt+2 -> stage (kt+2)%3 (consumed at kt-1, now free)
        if (kt + 2 < NK) issue(kt + 2);
    }

    // epilogue
    const int gid = lane >> 2;
    const int tig = lane & 3;
#pragma unroll
    for (int i = 0; i < 2; i++) {
#pragma unroll
        for (int h = 0; h < 2; h++) {
            int mrow = m0 + wm * 32 + i * 16 + gid + 8 * h;
            if (mrow >= cnt) continue;
            int slot = slots[mrow];
            if (MODE == 0) {
                __nv_bfloat16* hr = g_h2hi + (size_t)slot * HIDDEN + n0;
                __nv_bfloat16* lr = g_h2lo + (size_t)slot * HIDDEN + n0;
#pragma unroll
                for (int j = 0; j < 4; j++) {
                    int col = wn * 32 + j * 8 + 2 * tig;
#pragma unroll
                    for (int q = 0; q < 2; q++) {
                        float v = acc[i][j][h * 2 + q];
                        v = fmaxf(v, 0.f);
                        v = v * v;
                        __nv_bfloat16 hh = __float2bfloat16(v);
                        __nv_bfloat16 ll = __float2bfloat16(v - __bfloat162float(hh));
                        hr[col + q] = hh;
                        lr[col + q] = ll;
                    }
                }
            } else {
                float wgt = g_w[slot];
                int token = slot >> 1;
                float* orow = out + (size_t)token * DIM + n0;
#pragma unroll
                for (int j = 0; j < 4; j++) {
                    int col = wn * 32 + j * 8 + 2 * tig;
                    atomicAdd(&orow[col + 0], wgt * acc[i][j][h * 2 + 0]);
                    atomicAdd(&orow[col + 1], wgt * acc[i][j][h * 2 + 1]);
                }
            }
        }
    }
}

// ---------------- launch ------------------------------------------------------
extern "C" void kernel_launch(void* const* d_in, const int* in_sizes, int n_in,
                              void* d_out, int out_size) {
    const float* x = (const float*)d_in[0];
    const float* Wr = (const float*)d_in[1];
    const float* Wfc = (const float*)d_in[2];
    const float* Wpj = (const float*)d_in[3];
    float* out = (float*)d_out;

    cudaFuncSetAttribute(moe_mma_gemm<DIM, HIDDEN, 0>,
                         cudaFuncAttributeMaxDynamicSharedMemorySize, SMEM_TOTAL);
    cudaFuncSetAttribute(moe_mma_gemm<HIDDEN, DIM, 1>,
                         cudaFuncAttributeMaxDynamicSharedMemorySize, SMEM_TOTAL);

    zero_cnt_kernel<<<1, 32>>>();
    zero_out_kernel<<<(out_size / 4 + 255) / 256, 256>>>(out, out_size);
    router_kernel<<<TOKENS / 8, 256>>>(x, Wr);

    int n4x = TOKENS * DIM / 4;
    int n4w = NE * HIDDEN * DIM / 4;
    split_kernel<0><<<(n4x + 1023) / 1024, 256>>>(x, n4x);
    split_kernel<1><<<(n4w + 1023) / 1024, 256>>>(Wfc, n4w);
    split_kernel<2><<<(n4w + 1023) / 1024, 256>>>(Wpj, n4w);

    // fc: N=HIDDEN, K=DIM
    moe_mma_gemm<DIM, HIDDEN, 0>
        <<<dim3(HIDDEN / 128, TOKENS / 128, NE), 512, SMEM_TOTAL>>>(out);
    // proj: N=DIM, K=HIDDEN  (accumulates directly into out)
    moe_mma_gemm<HIDDEN, DIM, 1>
        <<<dim3(DIM / 128, TOKENS / 128, NE), 512, SMEM_TOTAL>>>(out);
}

// round 9
// speedup vs baseline: 1.1834x; 1.0852x over previous
#include <cuda_runtime.h>
#include <cuda_bf16.h>
#include <math.h>
#include <stdint.h>

#define DIM 1024
#define HIDDEN 2048
#define NE 8
#define TOKENS 2048
#define NSLOT (2*TOKENS)

// ---------------- scratch (static device globals; no runtime alloc) ----------
__device__ int   g_cnt[NE];
__device__ int   g_slots[NE * TOKENS];
__device__ float g_w[NSLOT];

__device__ __nv_bfloat16 g_xhi[(size_t)TOKENS * DIM];
__device__ __nv_bfloat16 g_xlo[(size_t)TOKENS * DIM];
__device__ __nv_bfloat16 g_wfchi[(size_t)NE * HIDDEN * DIM];
__device__ __nv_bfloat16 g_wfclo[(size_t)NE * HIDDEN * DIM];
__device__ __nv_bfloat16 g_wpjhi[(size_t)NE * DIM * HIDDEN];
__device__ __nv_bfloat16 g_wpjlo[(size_t)NE * DIM * HIDDEN];
__device__ __nv_bfloat16 g_h2hi[(size_t)NSLOT * HIDDEN];
__device__ __nv_bfloat16 g_h2lo[(size_t)NSLOT * HIDDEN];

// ---------------- helpers -----------------------------------------------------
__device__ __forceinline__ uint32_t smem_u32(const void* p) {
    uint32_t a;
    asm("{ .reg .u64 t; cvta.to.shared.u64 t, %1; cvt.u32.u64 %0, t; }"
        : "=r"(a) : "l"(p));
    return a;
}
__device__ __forceinline__ uint32_t sw128(uint32_t b) { return b ^ ((b >> 3) & 0x70); }

__device__ __forceinline__ void ldm_x4(uint32_t* r, uint32_t addr) {
    asm volatile("ldmatrix.sync.aligned.m8n8.x4.shared.b16 {%0,%1,%2,%3}, [%4];"
                 : "=r"(r[0]), "=r"(r[1]), "=r"(r[2]), "=r"(r[3]) : "r"(addr));
}
__device__ __forceinline__ void mma_bf16(float* d, const uint32_t* a, const uint32_t* b) {
    asm volatile(
        "mma.sync.aligned.m16n8k16.row.col.f32.bf16.bf16.f32 "
        "{%0,%1,%2,%3}, {%4,%5,%6,%7}, {%8,%9}, {%0,%1,%2,%3};"
        : "+f"(d[0]), "+f"(d[1]), "+f"(d[2]), "+f"(d[3])
        : "r"(a[0]), "r"(a[1]), "r"(a[2]), "r"(a[3]), "r"(b[0]), "r"(b[1]));
}
__device__ __forceinline__ void cp16(uint32_t dst, const void* src, uint32_t srcsize) {
    asm volatile("cp.async.cg.shared.global [%0], [%1], 16, %2;"
                 :: "r"(dst), "l"(src), "r"(srcsize) : "memory");
}
__device__ __forceinline__ void cp_commit() {
    asm volatile("cp.async.commit_group;" ::: "memory");
}
template <int N>
__device__ __forceinline__ void cp_wait() {
    asm volatile("cp.async.wait_group %0;" :: "n"(N) : "memory");
}

// ---------------- zero counters / zero output --------------------------------
__global__ void zero_cnt_kernel() {
    if (threadIdx.x < NE) g_cnt[threadIdx.x] = 0;
}
__global__ void zero_out_kernel(float* __restrict__ out, int out_size) {
    int i = blockIdx.x * blockDim.x + threadIdx.x;
    int n4 = out_size >> 2;
    if (i < n4) ((float4*)out)[i] = make_float4(0.f, 0.f, 0.f, 0.f);
    if (i == 0) {
        for (int j = n4 << 2; j < out_size; j++) out[j] = 0.f;
    }
}

// ---------------- fp32 -> bf16 hi/lo split (4 float4 per thread) --------------
template <int WHICH>  // 0 = x, 1 = W_fc, 2 = W_proj
__global__ void split_kernel(const float* __restrict__ src, int n4) {
    __nv_bfloat16* hi = (WHICH == 0) ? g_xhi : (WHICH == 1) ? g_wfchi : g_wpjhi;
    __nv_bfloat16* lo = (WHICH == 0) ? g_xlo : (WHICH == 1) ? g_wfclo : g_wpjlo;
    int base = blockIdx.x * (blockDim.x * 4) + threadIdx.x;
#pragma unroll
    for (int k = 0; k < 4; k++) {
        int i = base + k * blockDim.x;
        if (i >= n4) return;
        float4 v = ((const float4*)src)[i];
        __nv_bfloat16 h0 = __float2bfloat16(v.x);
        __nv_bfloat16 h1 = __float2bfloat16(v.y);
        __nv_bfloat16 h2 = __float2bfloat16(v.z);
        __nv_bfloat16 h3 = __float2bfloat16(v.w);
        __nv_bfloat16 l0 = __float2bfloat16(v.x - __bfloat162float(h0));
        __nv_bfloat16 l1 = __float2bfloat16(v.y - __bfloat162float(h1));
        __nv_bfloat16 l2 = __float2bfloat16(v.z - __bfloat162float(h2));
        __nv_bfloat16 l3 = __float2bfloat16(v.w - __bfloat162float(h3));
        __nv_bfloat162* hp = (__nv_bfloat162*)(hi + (size_t)i * 4);
        __nv_bfloat162* lp = (__nv_bfloat162*)(lo + (size_t)i * 4);
        hp[0] = __nv_bfloat162(h0, h1); hp[1] = __nv_bfloat162(h2, h3);
        lp[0] = __nv_bfloat162(l0, l1); lp[1] = __nv_bfloat162(l2, l3);
    }
}

// ---------------- router ------------------------------------------------------
__global__ void router_kernel(const float* __restrict__ x,
                              const float* __restrict__ Wr) {
    int warp = threadIdx.x >> 5;
    int lane = threadIdx.x & 31;
    int t = blockIdx.x * 8 + warp;
    if (t >= TOKENS) return;

    float acc[NE];
#pragma unroll
    for (int e = 0; e < NE; e++) acc[e] = 0.f;
    const float* xr = x + (size_t)t * DIM;
    for (int d = lane; d < DIM; d += 32) {
        float xv = xr[d];
#pragma unroll
        for (int e = 0; e < NE; e++) acc[e] += xv * Wr[e * DIM + d];
    }
#pragma unroll
    for (int e = 0; e < NE; e++) {
#pragma unroll
        for (int o = 16; o > 0; o >>= 1)
            acc[e] += __shfl_xor_sync(0xffffffffu, acc[e], o);
    }
    if (lane == 0) {
        float mx = acc[0];
#pragma unroll
        for (int e = 1; e < NE; e++) mx = fmaxf(mx, acc[e]);
        float p[NE]; float Z = 0.f;
#pragma unroll
        for (int e = 0; e < NE; e++) { p[e] = expf(acc[e] - mx); Z += p[e]; }
        int i1 = 0; float b1 = -1.f;
#pragma unroll
        for (int e = 0; e < NE; e++) if (p[e] > b1) { b1 = p[e]; i1 = e; }
        int i2 = -1; float b2 = -1.f;
#pragma unroll
        for (int e = 0; e < NE; e++) if (e != i1 && p[e] > b2) { b2 = p[e]; i2 = e; }
        float p1 = b1 / Z, p2 = b2 / Z;
        float s = p1 + p2 + 1e-8f;
        int pos1 = atomicAdd(&g_cnt[i1], 1);
        g_slots[i1 * TOKENS + pos1] = 2 * t;
        g_w[2 * t] = p1 / s;
        int pos2 = atomicAdd(&g_cnt[i2], 1);
        g_slots[i2 * TOKENS + pos2] = 2 * t + 1;
        g_w[2 * t + 1] = p2 / s;
    }
}

// ---------------- HMMA grouped GEMM (128x64 tile, 2 CTAs/SM) ------------------
// C[128,64] fp32 = sum_K A*B with bf16 2-term split: hi*hi + hi*lo + lo*hi.
// 256 threads, 8 warps of 32x32 warp tiles (4 m-blocks x 2 n-blocks).
// 2-stage cp.async (stage = 48KB, total 96KB) -> 2 CTAs/SM for barrier overlap.
// ONE __syncthreads per k-slab: wait(all) -> sync -> issue(kt+1) -> compute(kt).
//   issue(kt+1) targets stage (kt+1)%2 = stage of slab kt-1; the sync proves
//   every warp finished compute(kt-1), so the overwrite is safe.
// MODE 0 (fc):   A = x[slot>>1],  K=DIM,   B = W_fc,  epi relu^2 -> h2 hi/lo
// MODE 1 (proj): A = h2[slot],    K=HIDDEN,B = W_proj, epi wgt*acc atomicAdd->out
#define OFF_AHI 0
#define OFF_ALO 16384
#define OFF_BHI 32768
#define OFF_BLO 40960
#define STAGE_BYTES 49152
#define NSTAGE 2
#define SMEM_TOTAL (NSTAGE * STAGE_BYTES)

template <int K, int NTOT, int MODE>
__global__ void __launch_bounds__(256, 2) moe_mma_gemm(float* __restrict__ out) {
    const int e = blockIdx.z;
    const int cnt = g_cnt[e];
    const int m0 = blockIdx.y * 128;
    if (m0 >= cnt) return;
    const int n0 = blockIdx.x * 64;
    const int* slots = g_slots + e * TOKENS;

    extern __shared__ char smem[];
    const uint32_t sb = smem_u32(smem);
    const int tid = threadIdx.x;
    const int lane = tid & 31;
    const int wid = tid >> 5;
    const int wm = wid & 3;       // m-block of 32 (0..3)
    const int wn = wid >> 2;      // n-block of 32 (0..1)

    const __nv_bfloat16* Ahi_base = (MODE == 0) ? g_xhi : g_h2hi;
    const __nv_bfloat16* Alo_base = (MODE == 0) ? g_xlo : g_h2lo;
    const __nv_bfloat16* Bhi_base = (MODE == 0) ? g_wfchi : g_wpjhi;
    const __nv_bfloat16* Blo_base = (MODE == 0) ? g_wfclo : g_wpjlo;

    // loader: c16 = 16B chunk of 128B row, r0l = base row (0..31)
    const int c16 = tid & 7;
    const int r0l = tid >> 3;

    // A: 4 row-passes (128 rows), B: 2 row-passes (64 rows)
    const __nv_bfloat16* aphi[4];
    const __nv_bfloat16* aplo[4];
    uint32_t asz[4];
    uint32_t aoff[4];
#pragma unroll
    for (int p = 0; p < 4; p++) {
        int row = r0l + 32 * p;
        aoff[p] = sw128((uint32_t)(row * 128 + c16 * 16));
        int m = m0 + row;
        if (m < cnt) {
            int slot = slots[m];
            int arow = (MODE == 0) ? (slot >> 1) : slot;
            aphi[p] = Ahi_base + (size_t)arow * K + c16 * 8;
            aplo[p] = Alo_base + (size_t)arow * K + c16 * 8;
            asz[p] = 16u;
        } else {
            aphi[p] = Ahi_base; aplo[p] = Alo_base; asz[p] = 0u;
        }
    }
    const __nv_bfloat16* bphi[2];
    const __nv_bfloat16* bplo[2];
    uint32_t boffs[2];
#pragma unroll
    for (int p = 0; p < 2; p++) {
        int row = r0l + 32 * p;
        boffs[p] = sw128((uint32_t)(row * 128 + c16 * 16));
        size_t bo = ((size_t)e * NTOT + n0 + row) * K + c16 * 8;
        bphi[p] = Bhi_base + bo;
        bplo[p] = Blo_base + bo;
    }

    // ldmatrix address components (within-tile byte offsets before swizzle)
    const uint32_t a_row = wm * 32 + (lane & 15);
    const uint32_t a_kb = (uint32_t)((lane >> 4) << 4);
    const uint32_t b_row = wn * 32 + (lane & 7) + ((lane >> 4) << 3);
    const uint32_t b_kb = (uint32_t)(((lane >> 3) & 1) << 4);

    float acc[2][4][4];
#pragma unroll
    for (int i = 0; i < 2; i++)
#pragma unroll
        for (int j = 0; j < 4; j++)
#pragma unroll
            for (int q = 0; q < 4; q++) acc[i][j][q] = 0.f;

    constexpr int NK = K / 64;

    auto issue = [&](int slab) {
        uint32_t base = sb + (slab & 1) * STAGE_BYTES;
        int kn = slab * 64;
#pragma unroll
        for (int p = 0; p < 4; p++) {
            cp16(base + OFF_AHI + aoff[p], aphi[p] + kn, asz[p]);
            cp16(base + OFF_ALO + aoff[p], aplo[p] + kn, asz[p]);
        }
#pragma unroll
        for (int p = 0; p < 2; p++) {
            cp16(base + OFF_BHI + boffs[p], bphi[p] + kn, 16u);
            cp16(base + OFF_BLO + boffs[p], bplo[p] + kn, 16u);
        }
        cp_commit();
    };

    issue(0);

    for (int kt = 0; kt < NK; kt++) {
        cp_wait<0>();          // slab kt fully landed
        __syncthreads();       // all warps past compute(kt-1): stage (kt+1)&1 free
        if (kt + 1 < NK) issue(kt + 1);  // overlaps with compute(kt)

        const uint32_t base = sb + (kt & 1) * STAGE_BYTES;
#pragma unroll
        for (int c = 0; c < 4; c++) {
            const uint32_t kb = (uint32_t)(c * 32);
            uint32_t ah[2][4], al[2][4], bh[2][4], bl[2][4];
#pragma unroll
            for (int i = 0; i < 2; i++) {
                uint32_t off = sw128((a_row + 16 * i) * 128 + kb + a_kb);
                ldm_x4(ah[i], base + OFF_AHI + off);
                ldm_x4(al[i], base + OFF_ALO + off);
            }
#pragma unroll
            for (int jj = 0; jj < 2; jj++) {
                uint32_t off = sw128((b_row + 16 * jj) * 128 + kb + b_kb);
                ldm_x4(bh[jj], base + OFF_BHI + off);
                ldm_x4(bl[jj], base + OFF_BLO + off);
            }
#pragma unroll
            for (int i = 0; i < 2; i++)
#pragma unroll
                for (int j = 0; j < 4; j++) {
                    const uint32_t* bhp = &bh[j >> 1][(j & 1) * 2];
                    const uint32_t* blp = &bl[j >> 1][(j & 1) * 2];
                    mma_bf16(acc[i][j], ah[i], bhp);
                    mma_bf16(acc[i][j], ah[i], blp);
                    mma_bf16(acc[i][j], al[i], bhp);
                }
        }
        __syncthreads();       // stage kt&1 consumed by all before next overwrite
    }

    // epilogue
    const int gid = lane >> 2;
    const int tig = lane & 3;
#pragma unroll
    for (int i = 0; i < 2; i++) {
#pragma unroll
        for (int h = 0; h < 2; h++) {
            int mrow = m0 + wm * 32 + i * 16 + gid + 8 * h;
            if (mrow >= cnt) continue;
            int slot = slots[mrow];
            if (MODE == 0) {
                __nv_bfloat16* hr = g_h2hi + (size_t)slot * HIDDEN + n0;
                __nv_bfloat16* lr = g_h2lo + (size_t)slot * HIDDEN + n0;
#pragma unroll
                for (int j = 0; j < 4; j++) {
                    int col = wn * 32 + j * 8 + 2 * tig;
#pragma unroll
                    for (int q = 0; q < 2; q++) {
                        float v = acc[i][j][h * 2 + q];
                        v = fmaxf(v, 0.f);
                        v = v * v;
                        __nv_bfloat16 hh = __float2bfloat16(v);
                        __nv_bfloat16 ll = __float2bfloat16(v - __bfloat162float(hh));
                        hr[col + q] = hh;
                        lr[col + q] = ll;
                    }
                }
            } else {
                float wgt = g_w[slot];
                int token = slot >> 1;
                float* orow = out + (size_t)token * DIM + n0;
#pragma unroll
                for (int j = 0; j < 4; j++) {
                    int col = wn * 32 + j * 8 + 2 * tig;
                    atomicAdd(&orow[col + 0], wgt * acc[i][j][h * 2 + 0]);
                    atomicAdd(&orow[col + 1], wgt * acc[i][j][h * 2 + 1]);
                }
            }
        }
    }
}

// ---------------- launch ------------------------------------------------------
extern "C" void kernel_launch(void* const* d_in, const int* in_sizes, int n_in,
                              void* d_out, int out_size) {
    const float* x = (const float*)d_in[0];
    const float* Wr = (const float*)d_in[1];
    const float* Wfc = (const float*)d_in[2];
    const float* Wpj = (const float*)d_in[3];
    float* out = (float*)d_out;

    cudaFuncSetAttribute(moe_mma_gemm<DIM, HIDDEN, 0>,
                         cudaFuncAttributeMaxDynamicSharedMemorySize, SMEM_TOTAL);
    cudaFuncSetAttribute(moe_mma_gemm<HIDDEN, DIM, 1>,
                         cudaFuncAttributeMaxDynamicSharedMemorySize, SMEM_TOTAL);

    zero_cnt_kernel<<<1, 32>>>();
    zero_out_kernel<<<(out_size / 4 + 255) / 256, 256>>>(out, out_size);
    router_kernel<<<TOKENS / 8, 256>>>(x, Wr);

    int n4x = TOKENS * DIM / 4;
    int n4w = NE * HIDDEN * DIM / 4;
    split_kernel<0><<<(n4x + 1023) / 1024, 256>>>(x, n4x);
    split_kernel<1><<<(n4w + 1023) / 1024, 256>>>(Wfc, n4w);
    split_kernel<2><<<(n4w + 1023) / 1024, 256>>>(Wpj, n4w);

    // fc: N=HIDDEN, K=DIM
    moe_mma_gemm<DIM, HIDDEN, 0>
        <<<dim3(HIDDEN / 64, TOKENS / 128, NE), 256, SMEM_TOTAL>>>(out);
    // proj: N=DIM, K=HIDDEN  (accumulates directly into out)
    moe_mma_gemm<HIDDEN, DIM, 1>
        <<<dim3(DIM / 64, TOKENS / 128, NE), 256, SMEM_TOTAL>>>(out);
}

// round 10
// speedup vs baseline: 1.2845x; 1.0855x over previous
#include <cuda_runtime.h>
#include <cuda_bf16.h>
#include <math.h>
#include <stdint.h>

#define DIM 1024
#define HIDDEN 2048
#define NE 8
#define TOKENS 2048
#define NSLOT (2*TOKENS)

// ---------------- scratch (static device globals; no runtime alloc) ----------
__device__ int   g_cnt[NE];
__device__ int   g_slots[NE * TOKENS];
__device__ float g_w[NSLOT];

__device__ __nv_bfloat16 g_xhi[(size_t)TOKENS * DIM];
__device__ __nv_bfloat16 g_xlo[(size_t)TOKENS * DIM];
__device__ __nv_bfloat16 g_wfchi[(size_t)NE * HIDDEN * DIM];
__device__ __nv_bfloat16 g_wfclo[(size_t)NE * HIDDEN * DIM];
__device__ __nv_bfloat16 g_wpjhi[(size_t)NE * DIM * HIDDEN];
__device__ __nv_bfloat16 g_wpjlo[(size_t)NE * DIM * HIDDEN];
__device__ __nv_bfloat16 g_h2hi[(size_t)NSLOT * HIDDEN];
__device__ __nv_bfloat16 g_h2lo[(size_t)NSLOT * HIDDEN];

// ---------------- helpers -----------------------------------------------------
__device__ __forceinline__ uint32_t smem_u32(const void* p) {
    uint32_t a;
    asm("{ .reg .u64 t; cvta.to.shared.u64 t, %1; cvt.u32.u64 %0, t; }"
        : "=r"(a) : "l"(p));
    return a;
}
__device__ __forceinline__ uint32_t sw128(uint32_t b) { return b ^ ((b >> 3) & 0x70); }

__device__ __forceinline__ void ldm_x4(uint32_t* r, uint32_t addr) {
    asm volatile("ldmatrix.sync.aligned.m8n8.x4.shared.b16 {%0,%1,%2,%3}, [%4];"
                 : "=r"(r[0]), "=r"(r[1]), "=r"(r[2]), "=r"(r[3]) : "r"(addr));
}
__device__ __forceinline__ void mma_bf16(float* d, const uint32_t* a, const uint32_t* b) {
    asm volatile(
        "mma.sync.aligned.m16n8k16.row.col.f32.bf16.bf16.f32 "
        "{%0,%1,%2,%3}, {%4,%5,%6,%7}, {%8,%9}, {%0,%1,%2,%3};"
        : "+f"(d[0]), "+f"(d[1]), "+f"(d[2]), "+f"(d[3])
        : "r"(a[0]), "r"(a[1]), "r"(a[2]), "r"(a[3]), "r"(b[0]), "r"(b[1]));
}
__device__ __forceinline__ void cp16(uint32_t dst, const void* src, uint32_t srcsize) {
    asm volatile("cp.async.cg.shared.global [%0], [%1], 16, %2;"
                 :: "r"(dst), "l"(src), "r"(srcsize) : "memory");
}
__device__ __forceinline__ void cp_commit() {
    asm volatile("cp.async.commit_group;" ::: "memory");
}
template <int N>
__device__ __forceinline__ void cp_wait() {
    asm volatile("cp.async.wait_group %0;" :: "n"(N) : "memory");
}

// ---------------- zero counters / zero output --------------------------------
__global__ void zero_cnt_kernel() {
    if (threadIdx.x < NE) g_cnt[threadIdx.x] = 0;
}
__global__ void zero_out_kernel(float* __restrict__ out, int out_size) {
    int i = blockIdx.x * blockDim.x + threadIdx.x;
    int n4 = out_size >> 2;
    if (i < n4) ((float4*)out)[i] = make_float4(0.f, 0.f, 0.f, 0.f);
    if (i == 0) {
        for (int j = n4 << 2; j < out_size; j++) out[j] = 0.f;
    }
}

// ---------------- fp32 -> bf16 hi/lo split (4 float4 per thread) --------------
template <int WHICH>  // 0 = x, 1 = W_fc, 2 = W_proj
__global__ void split_kernel(const float* __restrict__ src, int n4) {
    __nv_bfloat16* hi = (WHICH == 0) ? g_xhi : (WHICH == 1) ? g_wfchi : g_wpjhi;
    __nv_bfloat16* lo = (WHICH == 0) ? g_xlo : (WHICH == 1) ? g_wfclo : g_wpjlo;
    int base = blockIdx.x * (blockDim.x * 4) + threadIdx.x;
#pragma unroll
    for (int k = 0; k < 4; k++) {
        int i = base + k * blockDim.x;
        if (i >= n4) return;
        float4 v = ((const float4*)src)[i];
        __nv_bfloat16 h0 = __float2bfloat16(v.x);
        __nv_bfloat16 h1 = __float2bfloat16(v.y);
        __nv_bfloat16 h2 = __float2bfloat16(v.z);
        __nv_bfloat16 h3 = __float2bfloat16(v.w);
        __nv_bfloat16 l0 = __float2bfloat16(v.x - __bfloat162float(h0));
        __nv_bfloat16 l1 = __float2bfloat16(v.y - __bfloat162float(h1));
        __nv_bfloat16 l2 = __float2bfloat16(v.z - __bfloat162float(h2));
        __nv_bfloat16 l3 = __float2bfloat16(v.w - __bfloat162float(h3));
        __nv_bfloat162* hp = (__nv_bfloat162*)(hi + (size_t)i * 4);
        __nv_bfloat162* lp = (__nv_bfloat162*)(lo + (size_t)i * 4);
        hp[0] = __nv_bfloat162(h0, h1); hp[1] = __nv_bfloat162(h2, h3);
        lp[0] = __nv_bfloat162(l0, l1); lp[1] = __nv_bfloat162(l2, l3);
    }
}

// ---------------- router ------------------------------------------------------
__global__ void router_kernel(const float* __restrict__ x,
                              const float* __restrict__ Wr) {
    int warp = threadIdx.x >> 5;
    int lane = threadIdx.x & 31;
    int t = blockIdx.x * 8 + warp;
    if (t >= TOKENS) return;

    float acc[NE];
#pragma unroll
    for (int e = 0; e < NE; e++) acc[e] = 0.f;
    const float* xr = x + (size_t)t * DIM;
    for (int d = lane; d < DIM; d += 32) {
        float xv = xr[d];
#pragma unroll
        for (int e = 0; e < NE; e++) acc[e] += xv * Wr[e * DIM + d];
    }
#pragma unroll
    for (int e = 0; e < NE; e++) {
#pragma unroll
        for (int o = 16; o > 0; o >>= 1)
            acc[e] += __shfl_xor_sync(0xffffffffu, acc[e], o);
    }
    if (lane == 0) {
        float mx = acc[0];
#pragma unroll
        for (int e = 1; e < NE; e++) mx = fmaxf(mx, acc[e]);
        float p[NE]; float Z = 0.f;
#pragma unroll
        for (int e = 0; e < NE; e++) { p[e] = expf(acc[e] - mx); Z += p[e]; }
        int i1 = 0; float b1 = -1.f;
#pragma unroll
        for (int e = 0; e < NE; e++) if (p[e] > b1) { b1 = p[e]; i1 = e; }
        int i2 = -1; float b2 = -1.f;
#pragma unroll
        for (int e = 0; e < NE; e++) if (e != i1 && p[e] > b2) { b2 = p[e]; i2 = e; }
        float p1 = b1 / Z, p2 = b2 / Z;
        float s = p1 + p2 + 1e-8f;
        int pos1 = atomicAdd(&g_cnt[i1], 1);
        g_slots[i1 * TOKENS + pos1] = 2 * t;
        g_w[2 * t] = p1 / s;
        int pos2 = atomicAdd(&g_cnt[i2], 1);
        g_slots[i2 * TOKENS + pos2] = 2 * t + 1;
        g_w[2 * t + 1] = p2 / s;
    }
}

// ---------------- HMMA grouped GEMM (128x64 tile, 2 CTAs/SM) ------------------
// C[128,64] fp32 = sum_K A*B with bf16 2-term split: hi*hi + hi*lo + lo*hi.
// 256 threads, 8 warps of 32x32 warp tiles (4 m-blocks x 2 n-blocks).
// 2-stage cp.async (stage = 48KB, total 96KB) -> 2 CTAs/SM.
// SINGLE __syncthreads per k-slab:
//   {cp_wait<0>; sync; issue(kt+1); compute(kt)}.
//   Safety: issue(kt+2) runs only after the iter-(kt+1) sync, which requires
//   all warps past compute(kt) on stage kt&1 = the stage issue(kt+2) writes.
//   issue(kt+1) writes stage (kt+1)&1, disjoint from compute(kt)'s stage.
// MMA terms looped OUTERMOST (hh, hl, lh) so each accumulator's RAW chain has
// dependency distance 8 instead of 1.
// MODE 0 (fc):   A = x[slot>>1],  K=DIM,   B = W_fc,  epi relu^2 -> h2 hi/lo
// MODE 1 (proj): A = h2[slot],    K=HIDDEN,B = W_proj, epi wgt*acc atomicAdd->out
#define OFF_AHI 0
#define OFF_ALO 16384
#define OFF_BHI 32768
#define OFF_BLO 40960
#define STAGE_BYTES 49152
#define NSTAGE 2
#define SMEM_TOTAL (NSTAGE * STAGE_BYTES)

template <int K, int NTOT, int MODE>
__global__ void __launch_bounds__(256, 2) moe_mma_gemm(float* __restrict__ out) {
    const int e = blockIdx.z;
    const int cnt = g_cnt[e];
    const int m0 = blockIdx.y * 128;
    if (m0 >= cnt) return;
    const int n0 = blockIdx.x * 64;
    const int* slots = g_slots + e * TOKENS;

    extern __shared__ char smem[];
    const uint32_t sb = smem_u32(smem);
    const int tid = threadIdx.x;
    const int lane = tid & 31;
    const int wid = tid >> 5;
    const int wm = wid & 3;       // m-block of 32 (0..3)
    const int wn = wid >> 2;      // n-block of 32 (0..1)

    const __nv_bfloat16* Ahi_base = (MODE == 0) ? g_xhi : g_h2hi;
    const __nv_bfloat16* Alo_base = (MODE == 0) ? g_xlo : g_h2lo;
    const __nv_bfloat16* Bhi_base = (MODE == 0) ? g_wfchi : g_wpjhi;
    const __nv_bfloat16* Blo_base = (MODE == 0) ? g_wfclo : g_wpjlo;

    // loader: c16 = 16B chunk of 128B row, r0l = base row (0..31)
    const int c16 = tid & 7;
    const int r0l = tid >> 3;

    const __nv_bfloat16* aphi[4];
    const __nv_bfloat16* aplo[4];
    uint32_t asz[4];
    uint32_t aoff[4];
#pragma unroll
    for (int p = 0; p < 4; p++) {
        int row = r0l + 32 * p;
        aoff[p] = sw128((uint32_t)(row * 128 + c16 * 16));
        int m = m0 + row;
        if (m < cnt) {
            int slot = slots[m];
            int arow = (MODE == 0) ? (slot >> 1) : slot;
            aphi[p] = Ahi_base + (size_t)arow * K + c16 * 8;
            aplo[p] = Alo_base + (size_t)arow * K + c16 * 8;
            asz[p] = 16u;
        } else {
            aphi[p] = Ahi_base; aplo[p] = Alo_base; asz[p] = 0u;
        }
    }
    const __nv_bfloat16* bphi[2];
    const __nv_bfloat16* bplo[2];
    uint32_t boffs[2];
#pragma unroll
    for (int p = 0; p < 2; p++) {
        int row = r0l + 32 * p;
        boffs[p] = sw128((uint32_t)(row * 128 + c16 * 16));
        size_t bo = ((size_t)e * NTOT + n0 + row) * K + c16 * 8;
        bphi[p] = Bhi_base + bo;
        bplo[p] = Blo_base + bo;
    }

    // ldmatrix address components (within-tile byte offsets before swizzle)
    const uint32_t a_row = wm * 32 + (lane & 15);
    const uint32_t a_kb = (uint32_t)((lane >> 4) << 4);
    const uint32_t b_row = wn * 32 + (lane & 7) + ((lane >> 4) << 3);
    const uint32_t b_kb = (uint32_t)(((lane >> 3) & 1) << 4);

    float acc[2][4][4];
#pragma unroll
    for (int i = 0; i < 2; i++)
#pragma unroll
        for (int j = 0; j < 4; j++)
#pragma unroll
            for (int q = 0; q < 4; q++) acc[i][j][q] = 0.f;

    constexpr int NK = K / 64;

    auto issue = [&](int slab) {
        uint32_t base = sb + (slab & 1) * STAGE_BYTES;
        int kn = slab * 64;
#pragma unroll
        for (int p = 0; p < 4; p++) {
            cp16(base + OFF_AHI + aoff[p], aphi[p] + kn, asz[p]);
            cp16(base + OFF_ALO + aoff[p], aplo[p] + kn, asz[p]);
        }
#pragma unroll
        for (int p = 0; p < 2; p++) {
            cp16(base + OFF_BHI + boffs[p], bphi[p] + kn, 16u);
            cp16(base + OFF_BLO + boffs[p], bplo[p] + kn, 16u);
        }
        cp_commit();
    };

    issue(0);

    for (int kt = 0; kt < NK; kt++) {
        cp_wait<0>();          // own cp.async groups retired (slab kt data in)
        __syncthreads();       // publish slab kt; all warps past compute(kt-1)
        if (kt + 1 < NK) issue(kt + 1);  // disjoint stage; overlaps compute(kt)

        const uint32_t base = sb + (kt & 1) * STAGE_BYTES;
#pragma unroll
        for (int c = 0; c < 4; c++) {
            const uint32_t kb = (uint32_t)(c * 32);
            uint32_t ah[2][4], al[2][4], bh[2][4], bl[2][4];
#pragma unroll
            for (int i = 0; i < 2; i++) {
                uint32_t off = sw128((a_row + 16 * i) * 128 + kb + a_kb);
                ldm_x4(ah[i], base + OFF_AHI + off);
                ldm_x4(al[i], base + OFF_ALO + off);
            }
#pragma unroll
            for (int jj = 0; jj < 2; jj++) {
                uint32_t off = sw128((b_row + 16 * jj) * 128 + kb + b_kb);
                ldm_x4(bh[jj], base + OFF_BHI + off);
                ldm_x4(bl[jj], base + OFF_BLO + off);
            }
            // term-outermost: dependency distance 8 per accumulator
#pragma unroll
            for (int i = 0; i < 2; i++)
#pragma unroll
                for (int j = 0; j < 4; j++)
                    mma_bf16(acc[i][j], ah[i], &bh[j >> 1][(j & 1) * 2]);
#pragma unroll
            for (int i = 0; i < 2; i++)
#pragma unroll
                for (int j = 0; j < 4; j++)
                    mma_bf16(acc[i][j], ah[i], &bl[j >> 1][(j & 1) * 2]);
#pragma unroll
            for (int i = 0; i < 2; i++)
#pragma unroll
                for (int j = 0; j < 4; j++)
                    mma_bf16(acc[i][j], al[i], &bh[j >> 1][(j & 1) * 2]);
        }
    }

    // epilogue
    const int gid = lane >> 2;
    const int tig = lane & 3;
#pragma unroll
    for (int i = 0; i < 2; i++) {
#pragma unroll
        for (int h = 0; h < 2; h++) {
            int mrow = m0 + wm * 32 + i * 16 + gid + 8 * h;
            if (mrow >= cnt) continue;
            int slot = slots[mrow];
            if (MODE == 0) {
                __nv_bfloat16* hr = g_h2hi + (size_t)slot * HIDDEN + n0;
                __nv_bfloat16* lr = g_h2lo + (size_t)slot * HIDDEN + n0;
#pragma unroll
                for (int j = 0; j < 4; j++) {
                    int col = wn * 32 + j * 8 + 2 * tig;
                    float v0 = acc[i][j][h * 2 + 0];
                    float v1 = acc[i][j][h * 2 + 1];
                    v0 = fmaxf(v0, 0.f); v0 = v0 * v0;
                    v1 = fmaxf(v1, 0.f); v1 = v1 * v1;
                    __nv_bfloat16 h0 = __float2bfloat16(v0);
                    __nv_bfloat16 h1 = __float2bfloat16(v1);
                    __nv_bfloat16 l0 = __float2bfloat16(v0 - __bfloat162float(h0));
                    __nv_bfloat16 l1 = __float2bfloat16(v1 - __bfloat162float(h1));
                    *(__nv_bfloat162*)(hr + col) = __nv_bfloat162(h0, h1);
                    *(__nv_bfloat162*)(lr + col) = __nv_bfloat162(l0, l1);
                }
            } else {
                float wgt = g_w[slot];
                int token = slot >> 1;
                float* orow = out + (size_t)token * DIM + n0;
#pragma unroll
                for (int j = 0; j < 4; j++) {
                    int col = wn * 32 + j * 8 + 2 * tig;
                    atomicAdd(&orow[col + 0], wgt * acc[i][j][h * 2 + 0]);
                    atomicAdd(&orow[col + 1], wgt * acc[i][j][h * 2 + 1]);
                }
            }
        }
    }
}

// ---------------- launch ------------------------------------------------------
extern "C" void kernel_launch(void* const* d_in, const int* in_sizes, int n_in,
                              void* d_out, int out_size) {
    const float* x = (const float*)d_in[0];
    const float* Wr = (const float*)d_in[1];
    const float* Wfc = (const float*)d_in[2];
    const float* Wpj = (const float*)d_in[3];
    float* out = (float*)d_out;

    cudaFuncSetAttribute(moe_mma_gemm<DIM, HIDDEN, 0>,
                         cudaFuncAttributeMaxDynamicSharedMemorySize, SMEM_TOTAL);
    cudaFuncSetAttribute(moe_mma_gemm<HIDDEN, DIM, 1>,
                         cudaFuncAttributeMaxDynamicSharedMemorySize, SMEM_TOTAL);

    zero_cnt_kernel<<<1, 32>>>();
    zero_out_kernel<<<(out_size / 4 + 255) / 256, 256>>>(out, out_size);
    router_kernel<<<TOKENS / 8, 256>>>(x, Wr);

    int n4x = TOKENS * DIM / 4;
    int n4w = NE * HIDDEN * DIM / 4;
    split_kernel<0><<<(n4x + 1023) / 1024, 256>>>(x, n4x);
    split_kernel<1><<<(n4w + 1023) / 1024, 256>>>(Wfc, n4w);
    split_kernel<2><<<(n4w + 1023) / 1024, 256>>>(Wpj, n4w);

    // fc: N=HIDDEN, K=DIM
    moe_mma_gemm<DIM, HIDDEN, 0>
        <<<dim3(HIDDEN / 64, TOKENS / 128, NE), 256, SMEM_TOTAL>>>(out);
    // proj: N=DIM, K=HIDDEN  (accumulates directly into out)
    moe_mma_gemm<HIDDEN, DIM, 1>
        <<<dim3(DIM / 64, TOKENS / 128, NE), 256, SMEM_TOTAL>>>(out);
}

// round 11
// speedup vs baseline: 1.3477x; 1.0492x over previous
#include <cuda_runtime.h>
#include <cuda_bf16.h>
#include <math.h>
#include <stdint.h>

#define DIM 1024
#define HIDDEN 2048
#define NE 8
#define TOKENS 2048
#define NSLOT (2*TOKENS)

// ---------------- scratch (static device globals; no runtime alloc) ----------
__device__ int   g_cnt[NE];
__device__ int   g_slots[NE * TOKENS];
__device__ float g_w[NSLOT];

__device__ __nv_bfloat16 g_xhi[(size_t)TOKENS * DIM];
__device__ __nv_bfloat16 g_xlo[(size_t)TOKENS * DIM];
__device__ __nv_bfloat16 g_wfchi[(size_t)NE * HIDDEN * DIM];
__device__ __nv_bfloat16 g_wfclo[(size_t)NE * HIDDEN * DIM];
__device__ __nv_bfloat16 g_wpjhi[(size_t)NE * DIM * HIDDEN];
__device__ __nv_bfloat16 g_wpjlo[(size_t)NE * DIM * HIDDEN];
__device__ __nv_bfloat16 g_h2hi[(size_t)NSLOT * HIDDEN];
__device__ __nv_bfloat16 g_h2lo[(size_t)NSLOT * HIDDEN];

// ---------------- helpers -----------------------------------------------------
__device__ __forceinline__ uint32_t smem_u32(const void* p) {
    uint32_t a;
    asm("{ .reg .u64 t; cvta.to.shared.u64 t, %1; cvt.u32.u64 %0, t; }"
        : "=r"(a) : "l"(p));
    return a;
}
__device__ __forceinline__ uint32_t sw128(uint32_t b) { return b ^ ((b >> 3) & 0x70); }

__device__ __forceinline__ void ldm_x4(uint32_t* r, uint32_t addr) {
    asm volatile("ldmatrix.sync.aligned.m8n8.x4.shared.b16 {%0,%1,%2,%3}, [%4];"
                 : "=r"(r[0]), "=r"(r[1]), "=r"(r[2]), "=r"(r[3]) : "r"(addr));
}
__device__ __forceinline__ void mma_bf16(float* d, const uint32_t* a, const uint32_t* b) {
    asm volatile(
        "mma.sync.aligned.m16n8k16.row.col.f32.bf16.bf16.f32 "
        "{%0,%1,%2,%3}, {%4,%5,%6,%7}, {%8,%9}, {%0,%1,%2,%3};"
        : "+f"(d[0]), "+f"(d[1]), "+f"(d[2]), "+f"(d[3])
        : "r"(a[0]), "r"(a[1]), "r"(a[2]), "r"(a[3]), "r"(b[0]), "r"(b[1]));
}
__device__ __forceinline__ void cp16(uint32_t dst, const void* src, uint32_t srcsize) {
    asm volatile("cp.async.cg.shared.global [%0], [%1], 16, %2;"
                 :: "r"(dst), "l"(src), "r"(srcsize) : "memory");
}
__device__ __forceinline__ void cp_commit() {
    asm volatile("cp.async.commit_group;" ::: "memory");
}
template <int N>
__device__ __forceinline__ void cp_wait() {
    asm volatile("cp.async.wait_group %0;" :: "n"(N) : "memory");
}

// ---------------- zero counters + output (merged) -----------------------------
__global__ void zero_kernel(float* __restrict__ out, int out_size) {
    int i = blockIdx.x * blockDim.x + threadIdx.x;
    if (i == 0) {
#pragma unroll
        for (int e = 0; e < NE; e++) g_cnt[e] = 0;
        int n4 = out_size >> 2;
        for (int j = n4 << 2; j < out_size; j++) out[j] = 0.f;
    }
    int n4 = out_size >> 2;
    if (i < n4) ((float4*)out)[i] = make_float4(0.f, 0.f, 0.f, 0.f);
}

// ---------------- fp32 -> bf16 hi/lo split (merged: x, W_fc, W_proj) ----------
#define N4X (TOKENS * DIM / 4)
#define N4W (NE * HIDDEN * DIM / 4)
__global__ void split_all_kernel(const float* __restrict__ x,
                                 const float* __restrict__ Wfc,
                                 const float* __restrict__ Wpj) {
    int base = blockIdx.x * (blockDim.x * 4) + threadIdx.x;
#pragma unroll
    for (int k = 0; k < 4; k++) {
        int i = base + k * blockDim.x;
        if (i >= N4X + 2 * N4W) return;
        const float* src;
        __nv_bfloat16* hi;
        __nv_bfloat16* lo;
        int idx;
        if (i < N4X) {
            src = x; hi = g_xhi; lo = g_xlo; idx = i;
        } else if (i < N4X + N4W) {
            src = Wfc; hi = g_wfchi; lo = g_wfclo; idx = i - N4X;
        } else {
            src = Wpj; hi = g_wpjhi; lo = g_wpjlo; idx = i - N4X - N4W;
        }
        float4 v = ((const float4*)src)[idx];
        __nv_bfloat16 h0 = __float2bfloat16(v.x);
        __nv_bfloat16 h1 = __float2bfloat16(v.y);
        __nv_bfloat16 h2 = __float2bfloat16(v.z);
        __nv_bfloat16 h3 = __float2bfloat16(v.w);
        __nv_bfloat16 l0 = __float2bfloat16(v.x - __bfloat162float(h0));
        __nv_bfloat16 l1 = __float2bfloat16(v.y - __bfloat162float(h1));
        __nv_bfloat16 l2 = __float2bfloat16(v.z - __bfloat162float(h2));
        __nv_bfloat16 l3 = __float2bfloat16(v.w - __bfloat162float(h3));
        __nv_bfloat162* hp = (__nv_bfloat162*)(hi + (size_t)idx * 4);
        __nv_bfloat162* lp = (__nv_bfloat162*)(lo + (size_t)idx * 4);
        hp[0] = __nv_bfloat162(h0, h1); hp[1] = __nv_bfloat162(h2, h3);
        lp[0] = __nv_bfloat162(l0, l1); lp[1] = __nv_bfloat162(l2, l3);
    }
}

// ---------------- router ------------------------------------------------------
__global__ void router_kernel(const float* __restrict__ x,
                              const float* __restrict__ Wr) {
    int warp = threadIdx.x >> 5;
    int lane = threadIdx.x & 31;
    int t = blockIdx.x * 8 + warp;
    if (t >= TOKENS) return;

    float acc[NE];
#pragma unroll
    for (int e = 0; e < NE; e++) acc[e] = 0.f;
    const float* xr = x + (size_t)t * DIM;
    for (int d = lane; d < DIM; d += 32) {
        float xv = xr[d];
#pragma unroll
        for (int e = 0; e < NE; e++) acc[e] += xv * Wr[e * DIM + d];
    }
#pragma unroll
    for (int e = 0; e < NE; e++) {
#pragma unroll
        for (int o = 16; o > 0; o >>= 1)
            acc[e] += __shfl_xor_sync(0xffffffffu, acc[e], o);
    }
    if (lane == 0) {
        float mx = acc[0];
#pragma unroll
        for (int e = 1; e < NE; e++) mx = fmaxf(mx, acc[e]);
        float p[NE]; float Z = 0.f;
#pragma unroll
        for (int e = 0; e < NE; e++) { p[e] = expf(acc[e] - mx); Z += p[e]; }
        int i1 = 0; float b1 = -1.f;
#pragma unroll
        for (int e = 0; e < NE; e++) if (p[e] > b1) { b1 = p[e]; i1 = e; }
        int i2 = -1; float b2 = -1.f;
#pragma unroll
        for (int e = 0; e < NE; e++) if (e != i1 && p[e] > b2) { b2 = p[e]; i2 = e; }
        float p1 = b1 / Z, p2 = b2 / Z;
        float s = p1 + p2 + 1e-8f;
        int pos1 = atomicAdd(&g_cnt[i1], 1);
        g_slots[i1 * TOKENS + pos1] = 2 * t;
        g_w[2 * t] = p1 / s;
        int pos2 = atomicAdd(&g_cnt[i2], 1);
        g_slots[i2 * TOKENS + pos2] = 2 * t + 1;
        g_w[2 * t + 1] = p2 / s;
    }
}

// ---------------- HMMA grouped GEMM (128x64 tile, 2 CTAs/SM, de-phased) -------
// C[128,64] fp32 = sum_K A*B with bf16 2-term split: hi*hi + hi*lo + lo*hi.
// 256 threads, 8 warps of 32x32 warp tiles. 2-stage cp.async (96KB) -> 2 CTAs/SM.
// Single __syncthreads per k-slab (see R10 proof).
// DE-PHASING: odd-parity CTAs iterate k-slabs rotated by NK/2 so that the two
// co-resident CTAs' barriers/DRAM bursts don't align. NK even => the processed
// slab sequence still alternates stages (stage = slab & 1).
// MODE 0 (fc):   A = x[slot>>1],  K=DIM,   B = W_fc,  epi relu^2 -> h2 hi/lo
// MODE 1 (proj): A = h2[slot],    K=HIDDEN,B = W_proj, epi wgt*acc atomicAdd->out
#define OFF_AHI 0
#define OFF_ALO 16384
#define OFF_BHI 32768
#define OFF_BLO 40960
#define STAGE_BYTES 49152
#define NSTAGE 2
#define SMEM_TOTAL (NSTAGE * STAGE_BYTES)

template <int K, int NTOT, int MODE>
__global__ void __launch_bounds__(256, 2) moe_mma_gemm(float* __restrict__ out) {
    const int e = blockIdx.z;
    const int cnt = g_cnt[e];
    const int m0 = blockIdx.y * 128;
    if (m0 >= cnt) return;
    const int n0 = blockIdx.x * 64;
    const int* slots = g_slots + e * TOKENS;

    extern __shared__ char smem[];
    const uint32_t sb = smem_u32(smem);
    const int tid = threadIdx.x;
    const int lane = tid & 31;
    const int wid = tid >> 5;
    const int wm = wid & 3;       // m-block of 32 (0..3)
    const int wn = wid >> 2;      // n-block of 32 (0..1)

    const __nv_bfloat16* Ahi_base = (MODE == 0) ? g_xhi : g_h2hi;
    const __nv_bfloat16* Alo_base = (MODE == 0) ? g_xlo : g_h2lo;
    const __nv_bfloat16* Bhi_base = (MODE == 0) ? g_wfchi : g_wpjhi;
    const __nv_bfloat16* Blo_base = (MODE == 0) ? g_wfclo : g_wpjlo;

    // loader: c16 = 16B chunk of 128B row, r0l = base row (0..31)
    const int c16 = tid & 7;
    const int r0l = tid >> 3;

    const __nv_bfloat16* aphi[4];
    const __nv_bfloat16* aplo[4];
    uint32_t asz[4];
    uint32_t aoff[4];
#pragma unroll
    for (int p = 0; p < 4; p++) {
        int row = r0l + 32 * p;
        aoff[p] = sw128((uint32_t)(row * 128 + c16 * 16));
        int m = m0 + row;
        if (m < cnt) {
            int slot = slots[m];
            int arow = (MODE == 0) ? (slot >> 1) : slot;
            aphi[p] = Ahi_base + (size_t)arow * K + c16 * 8;
            aplo[p] = Alo_base + (size_t)arow * K + c16 * 8;
            asz[p] = 16u;
        } else {
            aphi[p] = Ahi_base; aplo[p] = Alo_base; asz[p] = 0u;
        }
    }
    const __nv_bfloat16* bphi[2];
    const __nv_bfloat16* bplo[2];
    uint32_t boffs[2];
#pragma unroll
    for (int p = 0; p < 2; p++) {
        int row = r0l + 32 * p;
        boffs[p] = sw128((uint32_t)(row * 128 + c16 * 16));
        size_t bo = ((size_t)e * NTOT + n0 + row) * K + c16 * 8;
        bphi[p] = Bhi_base + bo;
        bplo[p] = Blo_base + bo;
    }

    // ldmatrix address components (within-tile byte offsets before swizzle)
    const uint32_t a_row = wm * 32 + (lane & 15);
    const uint32_t a_kb = (uint32_t)((lane >> 4) << 4);
    const uint32_t b_row = wn * 32 + (lane & 7) + ((lane >> 4) << 3);
    const uint32_t b_kb = (uint32_t)(((lane >> 3) & 1) << 4);

    float acc[2][4][4];
#pragma unroll
    for (int i = 0; i < 2; i++)
#pragma unroll
        for (int j = 0; j < 4; j++)
#pragma unroll
            for (int q = 0; q < 4; q++) acc[i][j][q] = 0.f;

    constexpr int NK = K / 64;
    // de-phase co-resident CTAs: odd parity starts halfway through the k range
    const int phase = ((blockIdx.x + blockIdx.y) & 1) ? (NK / 2) : 0;

    auto issue = [&](int slab) {
        uint32_t base = sb + (slab & 1) * STAGE_BYTES;
        int kn = slab * 64;
#pragma unroll
        for (int p = 0; p < 4; p++) {
            cp16(base + OFF_AHI + aoff[p], aphi[p] + kn, asz[p]);
            cp16(base + OFF_ALO + aoff[p], aplo[p] + kn, asz[p]);
        }
#pragma unroll
        for (int p = 0; p < 2; p++) {
            cp16(base + OFF_BHI + boffs[p], bphi[p] + kn, 16u);
            cp16(base + OFF_BLO + boffs[p], bplo[p] + kn, 16u);
        }
        cp_commit();
    };

    issue(phase);

    for (int kt = 0; kt < NK; kt++) {
        const int s = (kt + phase) & (NK - 1);       // actual slab this iter
        cp_wait<0>();          // slab s landed
        __syncthreads();       // publish; all warps past previous compute
        if (kt + 1 < NK) issue((kt + 1 + phase) & (NK - 1));

        const uint32_t base = sb + (s & 1) * STAGE_BYTES;
#pragma unroll
        for (int c = 0; c < 4; c++) {
            const uint32_t kb = (uint32_t)(c * 32);
            uint32_t ah[2][4], al[2][4], bh[2][4], bl[2][4];
#pragma unroll
            for (int i = 0; i < 2; i++) {
                uint32_t off = sw128((a_row + 16 * i) * 128 + kb + a_kb);
                ldm_x4(ah[i], base + OFF_AHI + off);
                ldm_x4(al[i], base + OFF_ALO + off);
            }
#pragma unroll
            for (int jj = 0; jj < 2; jj++) {
                uint32_t off = sw128((b_row + 16 * jj) * 128 + kb + b_kb);
                ldm_x4(bh[jj], base + OFF_BHI + off);
                ldm_x4(bl[jj], base + OFF_BLO + off);
            }
            // term-outermost: dependency distance 8 per accumulator
#pragma unroll
            for (int i = 0; i < 2; i++)
#pragma unroll
                for (int j = 0; j < 4; j++)
                    mma_bf16(acc[i][j], ah[i], &bh[j >> 1][(j & 1) * 2]);
#pragma unroll
            for (int i = 0; i < 2; i++)
#pragma unroll
                for (int j = 0; j < 4; j++)
                    mma_bf16(acc[i][j], ah[i], &bl[j >> 1][(j & 1) * 2]);
#pragma unroll
            for (int i = 0; i < 2; i++)
#pragma unroll
                for (int j = 0; j < 4; j++)
                    mma_bf16(acc[i][j], al[i], &bh[j >> 1][(j & 1) * 2]);
        }
    }

    // epilogue
    const int gid = lane >> 2;
    const int tig = lane & 3;
#pragma unroll
    for (int i = 0; i < 2; i++) {
#pragma unroll
        for (int h = 0; h < 2; h++) {
            int mrow = m0 + wm * 32 + i * 16 + gid + 8 * h;
            if (mrow >= cnt) continue;
            int slot = slots[mrow];
            if (MODE == 0) {
                __nv_bfloat16* hr = g_h2hi + (size_t)slot * HIDDEN + n0;
                __nv_bfloat16* lr = g_h2lo + (size_t)slot * HIDDEN + n0;
#pragma unroll
                for (int j = 0; j < 4; j++) {
                    int col = wn * 32 + j * 8 + 2 * tig;
                    float v0 = acc[i][j][h * 2 + 0];
                    float v1 = acc[i][j][h * 2 + 1];
                    v0 = fmaxf(v0, 0.f); v0 = v0 * v0;
                    v1 = fmaxf(v1, 0.f); v1 = v1 * v1;
                    __nv_bfloat16 h0 = __float2bfloat16(v0);
                    __nv_bfloat16 h1 = __float2bfloat16(v1);
                    __nv_bfloat16 l0 = __float2bfloat16(v0 - __bfloat162float(h0));
                    __nv_bfloat16 l1 = __float2bfloat16(v1 - __bfloat162float(h1));
                    *(__nv_bfloat162*)(hr + col) = __nv_bfloat162(h0, h1);
                    *(__nv_bfloat162*)(lr + col) = __nv_bfloat162(l0, l1);
                }
            } else {
                float wgt = g_w[slot];
                int token = slot >> 1;
                float* orow = out + (size_t)token * DIM + n0;
#pragma unroll
                for (int j = 0; j < 4; j++) {
                    int col = wn * 32 + j * 8 + 2 * tig;
                    atomicAdd(&orow[col + 0], wgt * acc[i][j][h * 2 + 0]);
                    atomicAdd(&orow[col + 1], wgt * acc[i][j][h * 2 + 1]);
                }
            }
        }
    }
}

// ---------------- launch ------------------------------------------------------
extern "C" void kernel_launch(void* const* d_in, const int* in_sizes, int n_in,
                              void* d_out, int out_size) {
    const float* x = (const float*)d_in[0];
    const float* Wr = (const float*)d_in[1];
    const float* Wfc = (const float*)d_in[2];
    const float* Wpj = (const float*)d_in[3];
    float* out = (float*)d_out;

    cudaFuncSetAttribute(moe_mma_gemm<DIM, HIDDEN, 0>,
                         cudaFuncAttributeMaxDynamicSharedMemorySize, SMEM_TOTAL);
    cudaFuncSetAttribute(moe_mma_gemm<HIDDEN, DIM, 1>,
                         cudaFuncAttributeMaxDynamicSharedMemorySize, SMEM_TOTAL);

    zero_kernel<<<(out_size / 4 + 255) / 256, 256>>>(out, out_size);
    router_kernel<<<TOKENS / 8, 256>>>(x, Wr);

    int n4all = N4X + 2 * N4W;
    split_all_kernel<<<(n4all + 1023) / 1024, 256>>>(x, Wfc, Wpj);

    // fc: N=HIDDEN, K=DIM
    moe_mma_gemm<DIM, HIDDEN, 0>
        <<<dim3(HIDDEN / 64, TOKENS / 128, NE), 256, SMEM_TOTAL>>>(out);
    // proj: N=DIM, K=HIDDEN  (accumulates directly into out)
    moe_mma_gemm<HIDDEN, DIM, 1>
        <<<dim3(DIM / 64, TOKENS / 128, NE), 256, SMEM_TOTAL>>>(out);
}

// round 12
// speedup vs baseline: 1.4613x; 1.0843x over previous
#include <cuda_runtime.h>
#include <cuda_bf16.h>
#include <math.h>
#include <stdint.h>

#define DIM 1024
#define HIDDEN 2048
#define NE 8
#define TOKENS 2048
#define NSLOT (2*TOKENS)

// ---------------- scratch (static device globals; no runtime alloc) ----------
__device__ int   g_cnt[NE];
__device__ int   g_slots[NE * TOKENS];
__device__ float g_w[NSLOT];

__device__ __nv_bfloat16 g_xhi[(size_t)TOKENS * DIM];
__device__ __nv_bfloat16 g_xlo[(size_t)TOKENS * DIM];
__device__ __nv_bfloat16 g_wfchi[(size_t)NE * HIDDEN * DIM];
__device__ __nv_bfloat16 g_wfclo[(size_t)NE * HIDDEN * DIM];
__device__ __nv_bfloat16 g_wpjhi[(size_t)NE * DIM * HIDDEN];
__device__ __nv_bfloat16 g_wpjlo[(size_t)NE * DIM * HIDDEN];
__device__ __nv_bfloat16 g_h2hi[(size_t)NSLOT * HIDDEN];
__device__ __nv_bfloat16 g_h2lo[(size_t)NSLOT * HIDDEN];

// ---------------- helpers -----------------------------------------------------
__device__ __forceinline__ uint32_t smem_u32(const void* p) {
    uint32_t a;
    asm("{ .reg .u64 t; cvta.to.shared.u64 t, %1; cvt.u32.u64 %0, t; }"
        : "=r"(a) : "l"(p));
    return a;
}
__device__ __forceinline__ uint32_t sw128(uint32_t b) { return b ^ ((b >> 3) & 0x70); }

__device__ __forceinline__ void ldm_x4(uint32_t* r, uint32_t addr) {
    asm volatile("ldmatrix.sync.aligned.m8n8.x4.shared.b16 {%0,%1,%2,%3}, [%4];"
                 : "=r"(r[0]), "=r"(r[1]), "=r"(r[2]), "=r"(r[3]) : "r"(addr));
}
__device__ __forceinline__ void mma_bf16(float* d, const uint32_t* a, const uint32_t* b) {
    asm volatile(
        "mma.sync.aligned.m16n8k16.row.col.f32.bf16.bf16.f32 "
        "{%0,%1,%2,%3}, {%4,%5,%6,%7}, {%8,%9}, {%0,%1,%2,%3};"
        : "+f"(d[0]), "+f"(d[1]), "+f"(d[2]), "+f"(d[3])
        : "r"(a[0]), "r"(a[1]), "r"(a[2]), "r"(a[3]), "r"(b[0]), "r"(b[1]));
}
__device__ __forceinline__ void cp16(uint32_t dst, const void* src, uint32_t srcsize) {
    asm volatile("cp.async.cg.shared.global [%0], [%1], 16, %2;"
                 :: "r"(dst), "l"(src), "r"(srcsize) : "memory");
}
__device__ __forceinline__ void cp_commit() {
    asm volatile("cp.async.commit_group;" ::: "memory");
}
template <int N>
__device__ __forceinline__ void cp_wait() {
    asm volatile("cp.async.wait_group %0;" :: "n"(N) : "memory");
}

// ---------------- zero counters + output (merged) -----------------------------
__global__ void zero_kernel(float* __restrict__ out, int out_size) {
    int i = blockIdx.x * blockDim.x + threadIdx.x;
    if (i == 0) {
        int n4 = out_size >> 2;
        for (int j = n4 << 2; j < out_size; j++) out[j] = 0.f;
    }
    int n4 = out_size >> 2;
    if (i < n4) ((float4*)out)[i] = make_float4(0.f, 0.f, 0.f, 0.f);
}
__global__ void zero_cnt_kernel() {
    if (threadIdx.x < NE) g_cnt[threadIdx.x] = 0;
}

// ---------------- fp32 -> bf16 hi/lo splits -----------------------------------
#define N4X (TOKENS * DIM / 4)
#define N4W (NE * HIDDEN * DIM / 4)

__device__ __forceinline__ void split_one(const float* __restrict__ src,
                                          __nv_bfloat16* __restrict__ hi,
                                          __nv_bfloat16* __restrict__ lo, int idx) {
    float4 v = ((const float4*)src)[idx];
    __nv_bfloat16 h0 = __float2bfloat16(v.x);
    __nv_bfloat16 h1 = __float2bfloat16(v.y);
    __nv_bfloat16 h2 = __float2bfloat16(v.z);
    __nv_bfloat16 h3 = __float2bfloat16(v.w);
    __nv_bfloat16 l0 = __float2bfloat16(v.x - __bfloat162float(h0));
    __nv_bfloat16 l1 = __float2bfloat16(v.y - __bfloat162float(h1));
    __nv_bfloat16 l2 = __float2bfloat16(v.z - __bfloat162float(h2));
    __nv_bfloat16 l3 = __float2bfloat16(v.w - __bfloat162float(h3));
    __nv_bfloat162* hp = (__nv_bfloat162*)(hi + (size_t)idx * 4);
    __nv_bfloat162* lp = (__nv_bfloat162*)(lo + (size_t)idx * 4);
    hp[0] = __nv_bfloat162(h0, h1); hp[1] = __nv_bfloat162(h2, h3);
    lp[0] = __nv_bfloat162(l0, l1); lp[1] = __nv_bfloat162(l2, l3);
}

// x + W_fc (needed before fc GEMM)
__global__ void split_xfc_kernel(const float* __restrict__ x,
                                 const float* __restrict__ Wfc) {
    int base = blockIdx.x * (blockDim.x * 4) + threadIdx.x;
#pragma unroll
    for (int k = 0; k < 4; k++) {
        int i = base + k * blockDim.x;
        if (i >= N4X + N4W) return;
        if (i < N4X) split_one(x, g_xhi, g_xlo, i);
        else         split_one(Wfc, g_wfchi, g_wfclo, i - N4X);
    }
}
// W_proj (only needed before proj GEMM; overlapped with fc)
__global__ void split_wpj_kernel(const float* __restrict__ Wpj) {
    int base = blockIdx.x * (blockDim.x * 4) + threadIdx.x;
#pragma unroll
    for (int k = 0; k < 4; k++) {
        int i = base + k * blockDim.x;
        if (i >= N4W) return;
        split_one(Wpj, g_wpjhi, g_wpjlo, i);
    }
}

// ---------------- router ------------------------------------------------------
__global__ void router_kernel(const float* __restrict__ x,
                              const float* __restrict__ Wr) {
    int warp = threadIdx.x >> 5;
    int lane = threadIdx.x & 31;
    int t = blockIdx.x * 8 + warp;
    if (t >= TOKENS) return;

    float acc[NE];
#pragma unroll
    for (int e = 0; e < NE; e++) acc[e] = 0.f;
    const float* xr = x + (size_t)t * DIM;
    for (int d = lane; d < DIM; d += 32) {
        float xv = xr[d];
#pragma unroll
        for (int e = 0; e < NE; e++) acc[e] += xv * Wr[e * DIM + d];
    }
#pragma unroll
    for (int e = 0; e < NE; e++) {
#pragma unroll
        for (int o = 16; o > 0; o >>= 1)
            acc[e] += __shfl_xor_sync(0xffffffffu, acc[e], o);
    }
    if (lane == 0) {
        float mx = acc[0];
#pragma unroll
        for (int e = 1; e < NE; e++) mx = fmaxf(mx, acc[e]);
        float p[NE]; float Z = 0.f;
#pragma unroll
        for (int e = 0; e < NE; e++) { p[e] = expf(acc[e] - mx); Z += p[e]; }
        int i1 = 0; float b1 = -1.f;
#pragma unroll
        for (int e = 0; e < NE; e++) if (p[e] > b1) { b1 = p[e]; i1 = e; }
        int i2 = -1; float b2 = -1.f;
#pragma unroll
        for (int e = 0; e < NE; e++) if (e != i1 && p[e] > b2) { b2 = p[e]; i2 = e; }
        float p1 = b1 / Z, p2 = b2 / Z;
        float s = p1 + p2 + 1e-8f;
        int pos1 = atomicAdd(&g_cnt[i1], 1);
        g_slots[i1 * TOKENS + pos1] = 2 * t;
        g_w[2 * t] = p1 / s;
        int pos2 = atomicAdd(&g_cnt[i2], 1);
        g_slots[i2 * TOKENS + pos2] = 2 * t + 1;
        g_w[2 * t + 1] = p2 / s;
    }
}

// ---------------- HMMA grouped GEMM (identical to R11 best) -------------------
#define OFF_AHI 0
#define OFF_ALO 16384
#define OFF_BHI 32768
#define OFF_BLO 40960
#define STAGE_BYTES 49152
#define NSTAGE 2
#define SMEM_TOTAL (NSTAGE * STAGE_BYTES)

template <int K, int NTOT, int MODE>
__global__ void __launch_bounds__(256, 2) moe_mma_gemm(float* __restrict__ out) {
    const int e = blockIdx.z;
    const int cnt = g_cnt[e];
    const int m0 = blockIdx.y * 128;
    if (m0 >= cnt) return;
    const int n0 = blockIdx.x * 64;
    const int* slots = g_slots + e * TOKENS;

    extern __shared__ char smem[];
    const uint32_t sb = smem_u32(smem);
    const int tid = threadIdx.x;
    const int lane = tid & 31;
    const int wid = tid >> 5;
    const int wm = wid & 3;
    const int wn = wid >> 2;

    const __nv_bfloat16* Ahi_base = (MODE == 0) ? g_xhi : g_h2hi;
    const __nv_bfloat16* Alo_base = (MODE == 0) ? g_xlo : g_h2lo;
    const __nv_bfloat16* Bhi_base = (MODE == 0) ? g_wfchi : g_wpjhi;
    const __nv_bfloat16* Blo_base = (MODE == 0) ? g_wfclo : g_wpjlo;

    const int c16 = tid & 7;
    const int r0l = tid >> 3;

    const __nv_bfloat16* aphi[4];
    const __nv_bfloat16* aplo[4];
    uint32_t asz[4];
    uint32_t aoff[4];
#pragma unroll
    for (int p = 0; p < 4; p++) {
        int row = r0l + 32 * p;
        aoff[p] = sw128((uint32_t)(row * 128 + c16 * 16));
        int m = m0 + row;
        if (m < cnt) {
            int slot = slots[m];
            int arow = (MODE == 0) ? (slot >> 1) : slot;
            aphi[p] = Ahi_base + (size_t)arow * K + c16 * 8;
            aplo[p] = Alo_base + (size_t)arow * K + c16 * 8;
            asz[p] = 16u;
        } else {
            aphi[p] = Ahi_base; aplo[p] = Alo_base; asz[p] = 0u;
        }
    }
    const __nv_bfloat16* bphi[2];
    const __nv_bfloat16* bplo[2];
    uint32_t boffs[2];
#pragma unroll
    for (int p = 0; p < 2; p++) {
        int row = r0l + 32 * p;
        boffs[p] = sw128((uint32_t)(row * 128 + c16 * 16));
        size_t bo = ((size_t)e * NTOT + n0 + row) * K + c16 * 8;
        bphi[p] = Bhi_base + bo;
        bplo[p] = Blo_base + bo;
    }

    const uint32_t a_row = wm * 32 + (lane & 15);
    const uint32_t a_kb = (uint32_t)((lane >> 4) << 4);
    const uint32_t b_row = wn * 32 + (lane & 7) + ((lane >> 4) << 3);
    const uint32_t b_kb = (uint32_t)(((lane >> 3) & 1) << 4);

    float acc[2][4][4];
#pragma unroll
    for (int i = 0; i < 2; i++)
#pragma unroll
        for (int j = 0; j < 4; j++)
#pragma unroll
            for (int q = 0; q < 4; q++) acc[i][j][q] = 0.f;

    constexpr int NK = K / 64;
    const int phase = ((blockIdx.x + blockIdx.y) & 1) ? (NK / 2) : 0;

    auto issue = [&](int slab) {
        uint32_t base = sb + (slab & 1) * STAGE_BYTES;
        int kn = slab * 64;
#pragma unroll
        for (int p = 0; p < 4; p++) {
            cp16(base + OFF_AHI + aoff[p], aphi[p] + kn, asz[p]);
            cp16(base + OFF_ALO + aoff[p], aplo[p] + kn, asz[p]);
        }
#pragma unroll
        for (int p = 0; p < 2; p++) {
            cp16(base + OFF_BHI + boffs[p], bphi[p] + kn, 16u);
            cp16(base + OFF_BLO + boffs[p], bplo[p] + kn, 16u);
        }
        cp_commit();
    };

    issue(phase);

    for (int kt = 0; kt < NK; kt++) {
        const int s = (kt + phase) & (NK - 1);
        cp_wait<0>();
        __syncthreads();
        if (kt + 1 < NK) issue((kt + 1 + phase) & (NK - 1));

        const uint32_t base = sb + (s & 1) * STAGE_BYTES;
#pragma unroll
        for (int c = 0; c < 4; c++) {
            const uint32_t kb = (uint32_t)(c * 32);
            uint32_t ah[2][4], al[2][4], bh[2][4], bl[2][4];
#pragma unroll
            for (int i = 0; i < 2; i++) {
                uint32_t off = sw128((a_row + 16 * i) * 128 + kb + a_kb);
                ldm_x4(ah[i], base + OFF_AHI + off);
                ldm_x4(al[i], base + OFF_ALO + off);
            }
#pragma unroll
            for (int jj = 0; jj < 2; jj++) {
                uint32_t off = sw128((b_row + 16 * jj) * 128 + kb + b_kb);
                ldm_x4(bh[jj], base + OFF_BHI + off);
                ldm_x4(bl[jj], base + OFF_BLO + off);
            }
#pragma unroll
            for (int i = 0; i < 2; i++)
#pragma unroll
                for (int j = 0; j < 4; j++)
                    mma_bf16(acc[i][j], ah[i], &bh[j >> 1][(j & 1) * 2]);
#pragma unroll
            for (int i = 0; i < 2; i++)
#pragma unroll
                for (int j = 0; j < 4; j++)
                    mma_bf16(acc[i][j], ah[i], &bl[j >> 1][(j & 1) * 2]);
#pragma unroll
            for (int i = 0; i < 2; i++)
#pragma unroll
                for (int j = 0; j < 4; j++)
                    mma_bf16(acc[i][j], al[i], &bh[j >> 1][(j & 1) * 2]);
        }
    }

    const int gid = lane >> 2;
    const int tig = lane & 3;
#pragma unroll
    for (int i = 0; i < 2; i++) {
#pragma unroll
        for (int h = 0; h < 2; h++) {
            int mrow = m0 + wm * 32 + i * 16 + gid + 8 * h;
            if (mrow >= cnt) continue;
            int slot = slots[mrow];
            if (MODE == 0) {
                __nv_bfloat16* hr = g_h2hi + (size_t)slot * HIDDEN + n0;
                __nv_bfloat16* lr = g_h2lo + (size_t)slot * HIDDEN + n0;
#pragma unroll
                for (int j = 0; j < 4; j++) {
                    int col = wn * 32 + j * 8 + 2 * tig;
                    float v0 = acc[i][j][h * 2 + 0];
                    float v1 = acc[i][j][h * 2 + 1];
                    v0 = fmaxf(v0, 0.f); v0 = v0 * v0;
                    v1 = fmaxf(v1, 0.f); v1 = v1 * v1;
                    __nv_bfloat16 h0 = __float2bfloat16(v0);
                    __nv_bfloat16 h1 = __float2bfloat16(v1);
                    __nv_bfloat16 l0 = __float2bfloat16(v0 - __bfloat162float(h0));
                    __nv_bfloat16 l1 = __float2bfloat16(v1 - __bfloat162float(h1));
                    *(__nv_bfloat162*)(hr + col) = __nv_bfloat162(h0, h1);
                    *(__nv_bfloat162*)(lr + col) = __nv_bfloat162(l0, l1);
                }
            } else {
                float wgt = g_w[slot];
                int token = slot >> 1;
                float* orow = out + (size_t)token * DIM + n0;
#pragma unroll
                for (int j = 0; j < 4; j++) {
                    int col = wn * 32 + j * 8 + 2 * tig;
                    atomicAdd(&orow[col + 0], wgt * acc[i][j][h * 2 + 0]);
                    atomicAdd(&orow[col + 1], wgt * acc[i][j][h * 2 + 1]);
                }
            }
        }
    }
}

// ---------------- launch (stream-fork overlap, graph-capturable) ---------------
extern "C" void kernel_launch(void* const* d_in, const int* in_sizes, int n_in,
                              void* d_out, int out_size) {
    const float* x = (const float*)d_in[0];
    const float* Wr = (const float*)d_in[1];
    const float* Wfc = (const float*)d_in[2];
    const float* Wpj = (const float*)d_in[3];
    float* out = (float*)d_out;

    // one-time host resources (created on the uncaptured correctness call,
    // reused during capture; host-side only, no device allocation)
    static cudaStream_t s2 = nullptr;
    static cudaEvent_t evFork = nullptr, evRouter = nullptr, evS2 = nullptr;
    if (s2 == nullptr) {
        cudaStreamCreateWithFlags(&s2, cudaStreamNonBlocking);
        cudaEventCreateWithFlags(&evFork, cudaEventDisableTiming);
        cudaEventCreateWithFlags(&evRouter, cudaEventDisableTiming);
        cudaEventCreateWithFlags(&evS2, cudaEventDisableTiming);
        cudaFuncSetAttribute(moe_mma_gemm<DIM, HIDDEN, 0>,
                             cudaFuncAttributeMaxDynamicSharedMemorySize, SMEM_TOTAL);
        cudaFuncSetAttribute(moe_mma_gemm<HIDDEN, DIM, 1>,
                             cudaFuncAttributeMaxDynamicSharedMemorySize, SMEM_TOTAL);
    }

    // main: counter zero (router dependency), then fork side stream
    zero_cnt_kernel<<<1, 32>>>();
    cudaEventRecord(evFork, 0);
    cudaStreamWaitEvent(s2, evFork, 0);

    // side stream: router -> (evRouter) -> zero out -> split W_proj -> (evS2)
    router_kernel<<<TOKENS / 8, 256, 0, s2>>>(x, Wr);
    cudaEventRecord(evRouter, s2);
    zero_kernel<<<(out_size / 4 + 255) / 256, 256, 0, s2>>>(out, out_size);
    split_wpj_kernel<<<(N4W + 1023) / 1024, 256, 0, s2>>>(Wpj);
    cudaEventRecord(evS2, s2);

    // main: split x + W_fc (concurrent with router)
    split_xfc_kernel<<<(N4X + N4W + 1023) / 1024, 256>>>(x, Wfc);

    // fc needs router + split_xfc
    cudaStreamWaitEvent(0, evRouter, 0);
    moe_mma_gemm<DIM, HIDDEN, 0>
        <<<dim3(HIDDEN / 64, TOKENS / 128, NE), 256, SMEM_TOTAL>>>(out);

    // proj needs fc + zero(out) + split_wpj
    cudaStreamWaitEvent(0, evS2, 0);
    moe_mma_gemm<HIDDEN, DIM, 1>
        <<<dim3(DIM / 64, TOKENS / 128, NE), 256, SMEM_TOTAL>>>(out);
}